// round 11
// baseline (speedup 1.0000x reference)
#include <cuda_runtime.h>
#include <cuda_bf16.h>
#include <cstdint>
#include <math.h>

#define BB 2
#define TT 1024
#define MM 1024
#define FF 1024
#define NHEAD 16
#define HH 64
#define SS 2048            // M + T
#define NH 1024            // N * H
#define SCALE 0.125f       // 1/sqrt(64)
#define NEGINF -1e30f

#define KW 2048            // storage width of split operands [p1|p2]

// ======================= scratch (device globals) =======================
__device__ float         g_qv[(size_t)BB * TT * NH];
__device__ __nv_bfloat16 g_qu[(size_t)BB * TT * NH];
__device__ __nv_bfloat16 g_kb[(size_t)BB * SS * NH];
__device__ __nv_bfloat16 g_vb[(size_t)BB * SS * NH];
__device__ float         g_r [(size_t)SS * NH];
__device__ float         g_logits[(size_t)BB * NHEAD * TT * SS];
__device__ int           g_qi[BB * TT];
__device__ int           g_ki[BB * SS];

__device__ __nv_bfloat16 g_kvs[(size_t)BB * SS * KW];       // kv splits [4096][2048]
__device__ __nv_bfloat16 g_rs [(size_t)SS * KW];            // rel splits [2048][2048]
__device__ __nv_bfloat16 g_wt [5 * (size_t)NH * KW];        // 5 weights [n][2048]
__device__ __nv_bfloat16 g_attnb[(size_t)BB * TT * NH];     // bf16 attn

// ======================= PTX helpers =======================
__device__ __forceinline__ uint32_t smem_to_u32(const void* p) {
    uint32_t a;
    asm("{ .reg .u64 t; cvta.to.shared.u64 t, %1; cvt.u32.u64 %0, t; }" : "=r"(a) : "l"(p));
    return a;
}
__device__ __forceinline__ uint32_t swz(uint32_t byte_off) {
    return byte_off ^ ((byte_off >> 3) & 0x70u);
}
#define CP_ASYNC16(dst, src) \
    asm volatile("cp.async.cg.shared.global [%0], [%1], 16;" :: "r"(dst), "l"(src))
#define CP_COMMIT() asm volatile("cp.async.commit_group;" ::: "memory")
#define CP_WAIT(n)  asm volatile("cp.async.wait_group %0;" :: "n"(n) : "memory")
#define LDSM_X4(r0, r1, r2, r3, addr) \
    asm volatile("ldmatrix.sync.aligned.m8n8.x4.shared.b16 {%0,%1,%2,%3}, [%4];" \
        : "=r"(r0), "=r"(r1), "=r"(r2), "=r"(r3) : "r"(addr))
#define MMA16816(d, a0, a1, a2, a3, b0, b1) \
    asm volatile("mma.sync.aligned.m16n8k16.row.col.f32.bf16.bf16.f32 " \
        "{%0,%1,%2,%3}, {%4,%5,%6,%7}, {%8,%9}, {%0,%1,%2,%3};" \
        : "+f"((d)[0]), "+f"((d)[1]), "+f"((d)[2]), "+f"((d)[3]) \
        : "r"(a0), "r"(a1), "r"(a2), "r"(a3), "r"(b0), "r"(b1))

// ======================= prep mega-kernel =======================
#define PREP_A 4096
#define PREP_B 2048
#define PREP_C 5120
#define PREP_GRID (PREP_A + PREP_B + PREP_C + 2)

__global__ void __launch_bounds__(256) prep(
    const float* __restrict__ x, const float* __restrict__ mem, const float* __restrict__ rel,
    const float* __restrict__ W0, const float* __restrict__ W1, const float* __restrict__ W2,
    const float* __restrict__ W3, const float* __restrict__ W4,
    const int* __restrict__ ep, const int* __restrict__ dones)
{
    __shared__ float tsm[32][33];
    __shared__ int   sb[256];
    const int g = blockIdx.x;
    const int tid = threadIdx.x;

    if (g < PREP_A) {
        int b = g >> 11, s = g & 2047;
        int f = tid * 4;
        const float* src = (s < MM) ? (mem + ((size_t)(b * MM + s)) * FF + f)
                                    : (x + ((size_t)(b * TT + (s - MM))) * FF + f);
        float4 a = *(const float4*)src;
        __nv_bfloat16 h1[4], h2[4];
        float av[4] = { a.x, a.y, a.z, a.w };
#pragma unroll
        for (int j = 0; j < 4; j++) {
            h1[j] = __float2bfloat16(av[j]);
            h2[j] = __float2bfloat16(av[j] - __bfloat162float(h1[j]));
        }
        size_t o = (size_t)g * KW + f;
        *(uint2*)&g_kvs[o] = *(uint2*)h1;
        *(uint2*)&g_kvs[o + 1024] = *(uint2*)h2;
    } else if (g < PREP_A + PREP_B) {
        int r = g - PREP_A;
        int f = tid * 4;
        float4 a = *(const float4*)(rel + (size_t)r * FF + f);
        __nv_bfloat16 h1[4], h2[4];
        float av[4] = { a.x, a.y, a.z, a.w };
#pragma unroll
        for (int j = 0; j < 4; j++) {
            h1[j] = __float2bfloat16(av[j]);
            h2[j] = __float2bfloat16(av[j] - __bfloat162float(h1[j]));
        }
        size_t o = (size_t)r * KW + f;
        *(uint2*)&g_rs[o] = *(uint2*)h1;
        *(uint2*)&g_rs[o + 1024] = *(uint2*)h2;
    } else if (g < PREP_A + PREP_B + PREP_C) {
        int tt = g - (PREP_A + PREP_B);
        int w = tt >> 10, tile = tt & 1023;
        int bx = tile & 31, by = tile >> 5;
        const float* Ws[5] = { W0, W1, W2, W3, W4 };
        const float* W = Ws[w];
        __nv_bfloat16* o = g_wt + (size_t)w * NH * KW;
#pragma unroll
        for (int i = 0; i < 4; i++) {
            int idx = tid + i * 256;
            int ky = idx >> 5, nx = idx & 31;
            tsm[ky][nx] = W[(size_t)(by * 32 + ky) * 1024 + bx * 32 + nx];
        }
        __syncthreads();
#pragma unroll
        for (int i = 0; i < 4; i++) {
            int idx = tid + i * 256;
            int nl = idx >> 5, kl = idx & 31;
            float a = tsm[kl][nl];
            __nv_bfloat16 h1 = __float2bfloat16(a);
            __nv_bfloat16 h2 = __float2bfloat16(a - __bfloat162float(h1));
            size_t ob = (size_t)(bx * 32 + nl) * KW + by * 32 + kl;
            o[ob] = h1; o[ob + 1024] = h2;
        }
    } else {
        int b = g - (PREP_A + PREP_B + PREP_C);
        int t4 = tid * 4;
        int d0 = dones[b * TT + t4], d1 = dones[b * TT + t4 + 1];
        int d2 = dones[b * TT + t4 + 2], d3 = dones[b * TT + t4 + 3];
        int l0 = d0, l1 = l0 + d1, l2 = l1 + d2, l3 = l2 + d3;
        sb[tid] = l3;
        __syncthreads();
        for (int off = 1; off < 256; off <<= 1) {
            int add = (tid >= off) ? sb[tid - off] : 0;
            __syncthreads();
            sb[tid] += add;
            __syncthreads();
        }
        int excl = sb[tid] - l3;
        int base = ep[b * MM + (MM - 1)];
        int q[4] = { base + excl + l0, base + excl + l1, base + excl + l2, base + excl + l3 };
#pragma unroll
        for (int j = 0; j < 4; j++) {
            g_qi[b * TT + t4 + j] = q[j];
            g_ki[b * SS + MM + t4 + j] = q[j];
            g_ki[b * SS + t4 + j] = ep[b * MM + t4 + j];
        }
    }
}

// ======================= HMMA core: multi-product stages =======================
// NPROD=3 (proj): stage {a1,a2,b1,b2}, products a1b1 + a1b2 + a2b1
// NPROD=2 (out):  stage {a, b1, b2},  products a b1 + a b2
#define SUBT 16384
#define NSTG 3

template <int NPROD>
struct Core {
    static constexpr int NSUB  = (NPROD == 3) ? 4 : 3;
    static constexpr int STAGE = NSUB * SUBT;
    uint32_t sbase;
    int tid, lane, wm, wn, lrow;
    uint32_t col8;
    float acc[4][4][4];

    __device__ __forceinline__ void init(char* smem) {
        sbase = smem_to_u32(smem);
        tid = threadIdx.x; lane = tid & 31;
        int warp = tid >> 5;
        wm = warp >> 2; wn = warp & 3;
        lrow = lane & 15; col8 = (lane >> 4) * 8;
#pragma unroll
        for (int mt = 0; mt < 4; mt++)
#pragma unroll
            for (int nt = 0; nt < 4; nt++)
#pragma unroll
                for (int e = 0; e < 4; e++) acc[mt][nt][e] = 0.f;
    }

    __device__ __forceinline__ void load_stage(int stage, int koff,
            const __nv_bfloat16* __restrict__ A, int ldA,
            const __nv_bfloat16* __restrict__ B, int ldB) {
        uint32_t base = sbase + stage * STAGE;
#pragma unroll
        for (int it = 0; it < NSUB * 4; it++) {
            int idx = tid + it * 256;
            int sub = idx >> 10;
            int rem = idx & 1023;
            int row = rem >> 3, seg = rem & 7;
            uint32_t off = swz((uint32_t)(row * 128 + seg * 16));
            const __nv_bfloat16* src;
            if (NPROD == 3) {
                if      (sub == 0) src = A + (size_t)row * ldA + koff + seg * 8;
                else if (sub == 1) src = A + (size_t)row * ldA + 1024 + koff + seg * 8;
                else if (sub == 2) src = B + (size_t)row * ldB + koff + seg * 8;
                else               src = B + (size_t)row * ldB + 1024 + koff + seg * 8;
            } else {
                if      (sub == 0) src = A + (size_t)row * ldA + koff + seg * 8;
                else if (sub == 1) src = B + (size_t)row * ldB + koff + seg * 8;
                else               src = B + (size_t)row * ldB + 1024 + koff + seg * 8;
            }
            CP_ASYNC16(base + sub * SUBT + off, src);
        }
    }

    __device__ __forceinline__ void compute(int stage) {
        uint32_t base = sbase + stage * STAGE;
        uint32_t a1b = base;
        uint32_t a2b = base + SUBT;                       // proj only
        uint32_t b1b = base + ((NPROD == 3) ? 2 : 1) * SUBT;
        uint32_t b2b = b1b + SUBT;
#pragma unroll
        for (int kk = 0; kk < 4; kk++) {
            uint32_t b1f[2][4], b2f[2][4];
#pragma unroll
            for (int bt = 0; bt < 2; bt++) {
                uint32_t ro = swz((uint32_t)((wn * 32 + bt * 16 + lrow) * 128 +
                                             (kk * 16 + col8) * 2));
                LDSM_X4(b1f[bt][0], b1f[bt][1], b1f[bt][2], b1f[bt][3], b1b + ro);
                LDSM_X4(b2f[bt][0], b2f[bt][1], b2f[bt][2], b2f[bt][3], b2b + ro);
            }
            uint32_t af[4][4];
#pragma unroll
            for (int mt = 0; mt < 4; mt++) {
                uint32_t ro = swz((uint32_t)((wm * 64 + mt * 16 + lrow) * 128 +
                                             (kk * 16 + col8) * 2));
                LDSM_X4(af[mt][0], af[mt][1], af[mt][2], af[mt][3], a1b + ro);
            }
            // product 1: a1 x b1
#pragma unroll
            for (int mt = 0; mt < 4; mt++)
#pragma unroll
                for (int bt = 0; bt < 2; bt++) {
                    MMA16816(acc[mt][2 * bt],     af[mt][0], af[mt][1], af[mt][2], af[mt][3],
                             b1f[bt][0], b1f[bt][2]);
                    MMA16816(acc[mt][2 * bt + 1], af[mt][0], af[mt][1], af[mt][2], af[mt][3],
                             b1f[bt][1], b1f[bt][3]);
                }
            // product 2: a1 x b2
#pragma unroll
            for (int mt = 0; mt < 4; mt++)
#pragma unroll
                for (int bt = 0; bt < 2; bt++) {
                    MMA16816(acc[mt][2 * bt],     af[mt][0], af[mt][1], af[mt][2], af[mt][3],
                             b2f[bt][0], b2f[bt][2]);
                    MMA16816(acc[mt][2 * bt + 1], af[mt][0], af[mt][1], af[mt][2], af[mt][3],
                             b2f[bt][1], b2f[bt][3]);
                }
            if (NPROD == 3) {
                // product 3: a2 x b1
#pragma unroll
                for (int mt = 0; mt < 4; mt++) {
                    uint32_t ro = swz((uint32_t)((wm * 64 + mt * 16 + lrow) * 128 +
                                                 (kk * 16 + col8) * 2));
                    LDSM_X4(af[mt][0], af[mt][1], af[mt][2], af[mt][3], a2b + ro);
                }
#pragma unroll
                for (int mt = 0; mt < 4; mt++)
#pragma unroll
                    for (int bt = 0; bt < 2; bt++) {
                        MMA16816(acc[mt][2 * bt],     af[mt][0], af[mt][1], af[mt][2], af[mt][3],
                                 b1f[bt][0], b1f[bt][2]);
                        MMA16816(acc[mt][2 * bt + 1], af[mt][0], af[mt][1], af[mt][2], af[mt][3],
                                 b1f[bt][1], b1f[bt][3]);
                    }
            }
        }
    }

    __device__ __forceinline__ void run(const __nv_bfloat16* A, int ldA,
                                        const __nv_bfloat16* B, int ldB) {
        load_stage(0, 0, A, ldA, B, ldB);
        CP_COMMIT();
        load_stage(1, 64, A, ldA, B, ldB);
        CP_COMMIT();
        int st = 0;
        for (int c = 0; c < 16; c++) {
            CP_WAIT(1);
            __syncthreads();
            compute(st);
            int nc = c + 2;
            int ns = st + 2; if (ns >= NSTG) ns -= NSTG;
            if (nc < 16) load_stage(ns, nc * 64, A, ldA, B, ldB);
            CP_COMMIT();
            st = (st + 1 == NSTG) ? 0 : st + 1;
        }
    }
};

#define PJ_SMEM (NSTG * 4 * SUBT)   // 192 KB
#define PO_SMEM (NSTG * 3 * SUBT)   // 144 KB

// ======================= merged projection GEMM (q, k, v, r) =======================
__global__ void __launch_bounds__(256, 1) proj_gemm(
    const float* __restrict__ bias_v, const float* __restrict__ bias_u)
{
    extern __shared__ char smem[];
    const int gy = blockIdx.y;
    const int c0 = blockIdx.x * 128;
    const size_t WS = (size_t)NH * KW;

    int gid, rt;
    if      (gy < 16) { gid = 0; rt = gy; }
    else if (gy < 48) { gid = 1; rt = gy - 16; }
    else if (gy < 80) { gid = 2; rt = gy - 48; }
    else              { gid = 3; rt = gy - 80; }
    const int r0 = rt * 128;

    const __nv_bfloat16* Atile;
    if (gid == 0) {
        int b = r0 >> 10;
        Atile = g_kvs + (size_t)(b * SS + MM + (r0 & 1023)) * KW;
    } else if (gid == 3) {
        Atile = g_rs + (size_t)r0 * KW;
    } else {
        Atile = g_kvs + (size_t)r0 * KW;
    }
    const __nv_bfloat16* Btile = g_wt + (size_t)gid * WS + (size_t)c0 * KW;

    Core<3> h;
    h.init(smem);
    h.run(Atile, KW, Btile, KW);

#pragma unroll
    for (int mt = 0; mt < 4; mt++) {
        int rbase = r0 + h.wm * 64 + mt * 16 + (h.lane >> 2);
#pragma unroll
        for (int nt = 0; nt < 4; nt++) {
            int cbase = c0 + h.wn * 32 + nt * 8 + (h.lane & 3) * 2;
#pragma unroll
            for (int e = 0; e < 4; e++) {
                int r = rbase + (e >> 1) * 8;
                int c = cbase + (e & 1);
                float vv = h.acc[mt][nt][e];
                size_t o = (size_t)r * 1024 + c;
                if (gid == 0) {
                    g_qv[o] = vv + bias_v[c];
                    g_qu[o] = __float2bfloat16(vv + bias_u[c]);
                } else if (gid == 1) {
                    g_kb[o] = __float2bfloat16(vv);
                } else if (gid == 2) {
                    g_vb[o] = __float2bfloat16(vv);
                } else {
                    g_r[o] = vv;
                }
            }
        }
    }
}

// ======================= output GEMM =======================
__global__ void __launch_bounds__(256, 1) out_gemm(const float* __restrict__ bo,
                                                   float* __restrict__ out)
{
    extern __shared__ char smem[];
    const int r0 = blockIdx.y * 128, c0 = blockIdx.x * 128;
    const __nv_bfloat16* Atile = g_attnb + (size_t)r0 * NH;
    const __nv_bfloat16* Btile = g_wt + 4 * (size_t)NH * KW + (size_t)c0 * KW;

    Core<2> h;
    h.init(smem);
    h.run(Atile, NH, Btile, KW);

#pragma unroll
    for (int mt = 0; mt < 4; mt++) {
        int rbase = r0 + h.wm * 64 + mt * 16 + (h.lane >> 2);
#pragma unroll
        for (int nt = 0; nt < 4; nt++) {
            int cbase = c0 + h.wn * 32 + nt * 8 + (h.lane & 3) * 2;
#pragma unroll
            for (int e = 0; e < 4; e++) {
                int r = rbase + (e >> 1) * 8;
                int c = cbase + (e & 1);
                out[(size_t)r * 1024 + c] = h.acc[mt][nt][e] + bo[c];
            }
        }
    }
}

// ======================= fused attention =======================
__global__ void __launch_bounds__(256) att_fused(const int* __restrict__ ep_idx)
{
    extern __shared__ float sm[];
    float* qu_s = sm;
    float* qv_s = qu_s + 64 * 65;
    float* k_s  = qv_s + 64 * 65;
    float* r_s  = k_s  + 64 * 65;
    float* rm_s = r_s + 128 * 65;
    float* rs_s = rm_s + 64;
    int* qi_s = (int*)(rs_s + 64);
    int* ki_s = qi_s + 64;

    const int tid = threadIdx.x;
    const int bn = blockIdx.x;
    const int b = bn >> 4, n = bn & 15;
    const int t0 = blockIdx.y * 64;
    const int ty = tid >> 4, tx = tid & 15;
    const int qbase = ty * 4, sbase = tx * 4;

    for (int e = tid; e < 4096; e += 256) {
        int q = e >> 6, h = e & 63;
        size_t row = (size_t)(b * TT + t0 + q) * NH + n * 64 + h;
        qu_s[q * 65 + h] = __bfloat162float(g_qu[row]);
        qv_s[q * 65 + h] = g_qv[row];
    }
    if (tid < 64) qi_s[tid] = g_qi[b * TT + t0 + tid];
    __syncthreads();

    const int qlo = qi_s[0], qhi = qi_s[63];
    const int causal_max = MM + t0 + 63;

    float rmax[4], rsum[4];
#pragma unroll
    for (int i = 0; i < 4; i++) { rmax[i] = -INFINITY; rsum[i] = 0.f; }

    for (int s0 = 0; s0 < SS; s0 += 64) {
        if (s0 > causal_max) break;
        {
            int klo = g_ki[b * SS + s0];
            int khi = g_ki[b * SS + s0 + 63];
            if (khi < qlo || klo > qhi) continue;
        }
        __syncthreads();
        for (int e = tid; e < 4096; e += 256) {
            int s = e >> 6, h = e & 63;
            k_s[s * 65 + h] = __bfloat162float(g_kb[(size_t)(b * SS + s0 + s) * NH + n * 64 + h]);
        }
        const int base = s0 - t0 + (TT - 64);
        for (int e = tid; e < 8192; e += 256) {
            int j = e >> 6, h = e & 63;
            int m = base + j; m = (m > SS - 1) ? SS - 1 : m; m = (m < 0) ? 0 : m;
            r_s[j * 65 + h] = g_r[(size_t)m * NH + n * 64 + h];
        }
        if (tid < 64) {
            int s = s0 + tid;
            ki_s[tid] = (s < MM) ? ep_idx[b * MM + s] : g_qi[b * TT + (s - MM)];
        }
        __syncthreads();

        float qk[4][4], bbx[4][4];
#pragma unroll
        for (int i = 0; i < 4; i++)
#pragma unroll
            for (int j = 0; j < 4; j++) { qk[i][j] = 0.f; bbx[i][j] = 0.f; }
        const int rrow0 = sbase - qbase + 60;
#pragma unroll 4
        for (int h = 0; h < 64; h++) {
            float au[4], av[4], kk4[4], rr[7];
#pragma unroll
            for (int i = 0; i < 4; i++) {
                au[i] = qu_s[(qbase + i) * 65 + h];
                av[i] = qv_s[(qbase + i) * 65 + h];
            }
#pragma unroll
            for (int j = 0; j < 4; j++) kk4[j] = k_s[(sbase + j) * 65 + h];
#pragma unroll
            for (int d = 0; d < 7; d++) rr[d] = r_s[(rrow0 + d) * 65 + h];
#pragma unroll
            for (int i = 0; i < 4; i++)
#pragma unroll
                for (int j = 0; j < 4; j++) {
                    qk[i][j]  = fmaf(au[i], kk4[j], qk[i][j]);
                    bbx[i][j] = fmaf(av[i], rr[j - i + 3], bbx[i][j]);
                }
        }
        float lv[4][4];
#pragma unroll
        for (int i = 0; i < 4; i++) {
            int tg = t0 + qbase + i;
#pragma unroll
            for (int j = 0; j < 4; j++) {
                int sg = s0 + sbase + j;
                float l = __bfloat162float(__float2bfloat16(qk[i][j])) * SCALE + bbx[i][j] * SCALE;
                bool ok = (sg <= MM + tg) && (qi_s[qbase + i] == ki_s[sbase + j]);
                l = ok ? l : NEGINF;
                lv[i][j] = l;
                g_logits[((size_t)bn * TT + tg) * SS + sg] = l;
            }
        }
#pragma unroll
        for (int i = 0; i < 4; i++) {
            float tm = fmaxf(fmaxf(lv[i][0], lv[i][1]), fmaxf(lv[i][2], lv[i][3]));
#pragma unroll
            for (int msk = 1; msk < 16; msk <<= 1)
                tm = fmaxf(tm, __shfl_xor_sync(0xffffffffu, tm, msk));
            float nm = fmaxf(rmax[i], tm);
            float ps = expf(lv[i][0] - nm) + expf(lv[i][1] - nm) +
                       expf(lv[i][2] - nm) + expf(lv[i][3] - nm);
#pragma unroll
            for (int msk = 1; msk < 16; msk <<= 1)
                ps += __shfl_xor_sync(0xffffffffu, ps, msk);
            rsum[i] = rsum[i] * expf(rmax[i] - nm) + ps;
            rmax[i] = nm;
        }
    }
    if (tx == 0) {
#pragma unroll
        for (int i = 0; i < 4; i++) {
            rm_s[qbase + i] = rmax[i];
            rs_s[qbase + i] = rsum[i];
        }
    }
    __syncthreads();

    float* p_s = qu_s;
    float* v_s = qv_s;
    float acc[4][4];
#pragma unroll
    for (int i = 0; i < 4; i++)
#pragma unroll
        for (int j = 0; j < 4; j++) acc[i][j] = 0.f;

    for (int s0 = 0; s0 < SS; s0 += 64) {
        if (s0 > causal_max) break;
        {
            int klo = g_ki[b * SS + s0];
            int khi = g_ki[b * SS + s0 + 63];
            if (khi < qlo || klo > qhi) continue;
        }
        __syncthreads();
        for (int e = tid; e < 4096; e += 256) {
            int q = e >> 6, s = e & 63;
            float L = g_logits[((size_t)bn * TT + t0 + q) * SS + s0 + s];
            float p = expf(L - rm_s[q]) / rs_s[q];
            p_s[q * 65 + s] = __bfloat162float(__float2bfloat16(p));
        }
        for (int e = tid; e < 4096; e += 256) {
            int s = e >> 6, h = e & 63;
            v_s[s * 65 + h] = __bfloat162float(g_vb[(size_t)(b * SS + s0 + s) * NH + n * 64 + h]);
        }
        __syncthreads();
#pragma unroll 8
        for (int s = 0; s < 64; s++) {
            float pv[4], vv[4];
#pragma unroll
            for (int i = 0; i < 4; i++) pv[i] = p_s[(ty * 4 + i) * 65 + s];
#pragma unroll
            for (int j = 0; j < 4; j++) vv[j] = v_s[s * 65 + tx * 4 + j];
#pragma unroll
            for (int i = 0; i < 4; i++)
#pragma unroll
                for (int j = 0; j < 4; j++)
                    acc[i][j] = fmaf(pv[i], vv[j], acc[i][j]);
        }
    }
#pragma unroll
    for (int i = 0; i < 4; i++) {
        int t = t0 + ty * 4 + i;
#pragma unroll
        for (int j = 0; j < 4; j++) {
            g_attnb[(size_t)(b * TT + t) * NH + n * 64 + tx * 4 + j] =
                __float2bfloat16(acc[i][j]);
        }
    }
}

// ======================= launch =======================
extern "C" void kernel_launch(void* const* d_in, const int* in_sizes, int n_in,
                              void* d_out, int out_size)
{
    const float* x    = (const float*)d_in[0];
    const float* rel  = (const float*)d_in[1];
    const float* mem  = (const float*)d_in[2];
    const int*   ep   = (const int*)d_in[3];
    const int*   dones= (const int*)d_in[4];
    const float* Wq   = (const float*)d_in[5];
    const float* Wk   = (const float*)d_in[6];
    const float* Wv   = (const float*)d_in[7];
    const float* Wr   = (const float*)d_in[8];
    const float* u    = (const float*)d_in[9];
    const float* v    = (const float*)d_in[10];
    const float* Wout = (const float*)d_in[11];
    const float* bo   = (const float*)d_in[12];
    float* out = (float*)d_out;
    (void)in_sizes; (void)n_in; (void)out_size;

    prep<<<PREP_GRID, 256>>>(x, mem, rel, Wq, Wk, Wv, Wr, Wout, ep, dones);

    cudaFuncSetAttribute(proj_gemm, cudaFuncAttributeMaxDynamicSharedMemorySize, PJ_SMEM);
    proj_gemm<<<dim3(8, 96), 256, PJ_SMEM>>>(v, u);

    const int att_smem = (3 * 64 * 65 + 128 * 65 + 128) * (int)sizeof(float) + 128 * (int)sizeof(int);
    cudaFuncSetAttribute(att_fused, cudaFuncAttributeMaxDynamicSharedMemorySize, att_smem);
    att_fused<<<dim3(BB * NHEAD, TT / 64), 256, att_smem>>>(ep);

    cudaFuncSetAttribute(out_gemm, cudaFuncAttributeMaxDynamicSharedMemorySize, PO_SMEM);
    out_gemm<<<dim3(8, 16), 256, PO_SMEM>>>(bo, out);
}

// round 14
// speedup vs baseline: 1.0033x; 1.0033x over previous
#include <cuda_runtime.h>
#include <cuda_bf16.h>
#include <cstdint>
#include <math.h>

#define BB 2
#define TT 1024
#define MM 1024
#define FF 1024
#define NHEAD 16
#define HH 64
#define SS 2048            // M + T
#define NH 1024            // N * H
#define SCALE 0.125f       // 1/sqrt(64)
#define NEGINF -1e30f

#define KW 2048            // storage width of split operands [p1|p2]

// ======================= scratch (device globals) =======================
__device__ float         g_qv[(size_t)BB * TT * NH];
__device__ __nv_bfloat16 g_qu[(size_t)BB * TT * NH];
__device__ __nv_bfloat16 g_kb[(size_t)BB * SS * NH];
__device__ __nv_bfloat16 g_vb[(size_t)BB * SS * NH];
__device__ float         g_r [(size_t)SS * NH];
__device__ float         g_logits[(size_t)BB * NHEAD * TT * SS];
__device__ int           g_qi[BB * TT];
__device__ int           g_ki[BB * SS];

__device__ __nv_bfloat16 g_kvs[(size_t)BB * SS * KW];       // kv splits [4096][2048]
__device__ __nv_bfloat16 g_rs [(size_t)SS * KW];            // rel splits [2048][2048]
__device__ __nv_bfloat16 g_wt [5 * (size_t)NH * KW];        // 5 weights [n][2048]
__device__ __nv_bfloat16 g_attnb[(size_t)BB * TT * NH];     // bf16 attn

// ======================= PTX helpers =======================
__device__ __forceinline__ uint32_t smem_to_u32(const void* p) {
    uint32_t a;
    asm("{ .reg .u64 t; cvta.to.shared.u64 t, %1; cvt.u32.u64 %0, t; }" : "=r"(a) : "l"(p));
    return a;
}
__device__ __forceinline__ uint32_t swz(uint32_t byte_off) {
    return byte_off ^ ((byte_off >> 3) & 0x70u);
}
#define CP_ASYNC16(dst, src) \
    asm volatile("cp.async.cg.shared.global [%0], [%1], 16;" :: "r"(dst), "l"(src))
#define CP_COMMIT() asm volatile("cp.async.commit_group;" ::: "memory")
#define CP_WAIT(n)  asm volatile("cp.async.wait_group %0;" :: "n"(n) : "memory")
#define LDSM_X4(r0, r1, r2, r3, addr) \
    asm volatile("ldmatrix.sync.aligned.m8n8.x4.shared.b16 {%0,%1,%2,%3}, [%4];" \
        : "=r"(r0), "=r"(r1), "=r"(r2), "=r"(r3) : "r"(addr))
#define MMA16816(d, a0, a1, a2, a3, b0, b1) \
    asm volatile("mma.sync.aligned.m16n8k16.row.col.f32.bf16.bf16.f32 " \
        "{%0,%1,%2,%3}, {%4,%5,%6,%7}, {%8,%9}, {%0,%1,%2,%3};" \
        : "+f"((d)[0]), "+f"((d)[1]), "+f"((d)[2]), "+f"((d)[3]) \
        : "r"(a0), "r"(a1), "r"(a2), "r"(a3), "r"(b0), "r"(b1))

// ======================= prep mega-kernel =======================
#define PREP_A 4096
#define PREP_B 2048
#define PREP_C 5120
#define PREP_GRID (PREP_A + PREP_B + PREP_C + 2)

__global__ void __launch_bounds__(256) prep(
    const float* __restrict__ x, const float* __restrict__ mem, const float* __restrict__ rel,
    const float* __restrict__ W0, const float* __restrict__ W1, const float* __restrict__ W2,
    const float* __restrict__ W3, const float* __restrict__ W4,
    const int* __restrict__ ep, const int* __restrict__ dones)
{
    __shared__ float tsm[32][33];
    __shared__ int   sb[256];
    const int g = blockIdx.x;
    const int tid = threadIdx.x;

    if (g < PREP_A) {
        int b = g >> 11, s = g & 2047;
        int f = tid * 4;
        const float* src = (s < MM) ? (mem + ((size_t)(b * MM + s)) * FF + f)
                                    : (x + ((size_t)(b * TT + (s - MM))) * FF + f);
        float4 a = *(const float4*)src;
        __nv_bfloat16 h1[4], h2[4];
        float av[4] = { a.x, a.y, a.z, a.w };
#pragma unroll
        for (int j = 0; j < 4; j++) {
            h1[j] = __float2bfloat16(av[j]);
            h2[j] = __float2bfloat16(av[j] - __bfloat162float(h1[j]));
        }
        size_t o = (size_t)g * KW + f;
        *(uint2*)&g_kvs[o] = *(uint2*)h1;
        *(uint2*)&g_kvs[o + 1024] = *(uint2*)h2;
    } else if (g < PREP_A + PREP_B) {
        int r = g - PREP_A;
        int f = tid * 4;
        float4 a = *(const float4*)(rel + (size_t)r * FF + f);
        __nv_bfloat16 h1[4], h2[4];
        float av[4] = { a.x, a.y, a.z, a.w };
#pragma unroll
        for (int j = 0; j < 4; j++) {
            h1[j] = __float2bfloat16(av[j]);
            h2[j] = __float2bfloat16(av[j] - __bfloat162float(h1[j]));
        }
        size_t o = (size_t)r * KW + f;
        *(uint2*)&g_rs[o] = *(uint2*)h1;
        *(uint2*)&g_rs[o + 1024] = *(uint2*)h2;
    } else if (g < PREP_A + PREP_B + PREP_C) {
        int tt = g - (PREP_A + PREP_B);
        int w = tt >> 10, tile = tt & 1023;
        int bx = tile & 31, by = tile >> 5;
        const float* Ws[5] = { W0, W1, W2, W3, W4 };
        const float* W = Ws[w];
        __nv_bfloat16* o = g_wt + (size_t)w * NH * KW;
#pragma unroll
        for (int i = 0; i < 4; i++) {
            int idx = tid + i * 256;
            int ky = idx >> 5, nx = idx & 31;
            tsm[ky][nx] = W[(size_t)(by * 32 + ky) * 1024 + bx * 32 + nx];
        }
        __syncthreads();
#pragma unroll
        for (int i = 0; i < 4; i++) {
            int idx = tid + i * 256;
            int nl = idx >> 5, kl = idx & 31;
            float a = tsm[kl][nl];
            __nv_bfloat16 h1 = __float2bfloat16(a);
            __nv_bfloat16 h2 = __float2bfloat16(a - __bfloat162float(h1));
            size_t ob = (size_t)(bx * 32 + nl) * KW + by * 32 + kl;
            o[ob] = h1; o[ob + 1024] = h2;
        }
    } else {
        int b = g - (PREP_A + PREP_B + PREP_C);
        int t4 = tid * 4;
        int d0 = dones[b * TT + t4], d1 = dones[b * TT + t4 + 1];
        int d2 = dones[b * TT + t4 + 2], d3 = dones[b * TT + t4 + 3];
        int l0 = d0, l1 = l0 + d1, l2 = l1 + d2, l3 = l2 + d3;
        sb[tid] = l3;
        __syncthreads();
        for (int off = 1; off < 256; off <<= 1) {
            int add = (tid >= off) ? sb[tid - off] : 0;
            __syncthreads();
            sb[tid] += add;
            __syncthreads();
        }
        int excl = sb[tid] - l3;
        int base = ep[b * MM + (MM - 1)];
        int q[4] = { base + excl + l0, base + excl + l1, base + excl + l2, base + excl + l3 };
#pragma unroll
        for (int j = 0; j < 4; j++) {
            g_qi[b * TT + t4 + j] = q[j];
            g_ki[b * SS + MM + t4 + j] = q[j];
            g_ki[b * SS + t4 + j] = ep[b * MM + t4 + j];
        }
    }
}

// ======================= HMMA core: packed K=32 multi-product stages =======================
// Stage layout (2 x 16 KB, SW128 128-byte rows, 64 elements/row):
//   Abuf row r: elements [0,32) = A[r, koff..koff+32), elements [32,64) = A[r, 1024+koff..+32)
//   Bbuf row r: elements [0,32) = B[r, koff..),        elements [32,64) = B[r, 1024+koff..)
// Products per k16 group: a1*b1, a1*b2, and (NPROD==3) a2*b1.
#define SUBT2 16384
#define NSTG 3
#define CORE_STAGE (2 * SUBT2)
#define CORE_SMEM (NSTG * CORE_STAGE)   // 96 KB -> 2 CTAs/SM

template <int NPROD>
struct Core {
    uint32_t sbase;
    int tid, lane, wm, wn, lrow;
    uint32_t col8;
    float acc[4][4][4];

    __device__ __forceinline__ void init(char* smem) {
        sbase = smem_to_u32(smem);
        tid = threadIdx.x; lane = tid & 31;
        int warp = tid >> 5;
        wm = warp >> 2; wn = warp & 3;
        lrow = lane & 15; col8 = (lane >> 4) * 8;
#pragma unroll
        for (int mt = 0; mt < 4; mt++)
#pragma unroll
            for (int nt = 0; nt < 4; nt++)
#pragma unroll
                for (int e = 0; e < 4; e++) acc[mt][nt][e] = 0.f;
    }

    __device__ __forceinline__ void load_stage(int stage, int koff,
            const __nv_bfloat16* __restrict__ A, int ldA,
            const __nv_bfloat16* __restrict__ B, int ldB) {
        uint32_t abuf = sbase + stage * CORE_STAGE;
        uint32_t bbuf = abuf + SUBT2;
#pragma unroll
        for (int it = 0; it < 8; it++) {
            int idx = tid + it * 256;              // 0..2047
            int isB = idx >> 10;
            int rem = idx & 1023;
            int row = rem >> 3, seg = rem & 7;
            if (!isB && NPROD == 2 && seg >= 4) continue;   // A duplicate half unused
            int col = (seg < 4) ? (koff + seg * 8) : (1024 + koff + (seg - 4) * 8);
            const __nv_bfloat16* src =
                isB ? (B + (size_t)row * ldB + col) : (A + (size_t)row * ldA + col);
            CP_ASYNC16((isB ? bbuf : abuf) + swz((uint32_t)(row * 128 + seg * 16)), src);
        }
    }

    __device__ __forceinline__ void compute(int stage) {
        uint32_t abuf = sbase + stage * CORE_STAGE;
        uint32_t bbuf = abuf + SUBT2;
#pragma unroll
        for (int kk = 0; kk < 2; kk++) {
            uint32_t b1f[2][4], b2f[2][4];
#pragma unroll
            for (int bt = 0; bt < 2; bt++) {
                uint32_t rb = (uint32_t)((wn * 32 + bt * 16 + lrow) * 128);
                LDSM_X4(b1f[bt][0], b1f[bt][1], b1f[bt][2], b1f[bt][3],
                        bbuf + swz(rb + (kk * 16 + col8) * 2));
                LDSM_X4(b2f[bt][0], b2f[bt][1], b2f[bt][2], b2f[bt][3],
                        bbuf + swz(rb + (32 + kk * 16 + col8) * 2));
            }
            uint32_t af[4][4];
#pragma unroll
            for (int mt = 0; mt < 4; mt++) {
                uint32_t ra = (uint32_t)((wm * 64 + mt * 16 + lrow) * 128);
                LDSM_X4(af[mt][0], af[mt][1], af[mt][2], af[mt][3],
                        abuf + swz(ra + (kk * 16 + col8) * 2));
            }
            // a1 x b1
#pragma unroll
            for (int mt = 0; mt < 4; mt++)
#pragma unroll
                for (int bt = 0; bt < 2; bt++) {
                    MMA16816(acc[mt][2 * bt],     af[mt][0], af[mt][1], af[mt][2], af[mt][3],
                             b1f[bt][0], b1f[bt][2]);
                    MMA16816(acc[mt][2 * bt + 1], af[mt][0], af[mt][1], af[mt][2], af[mt][3],
                             b1f[bt][1], b1f[bt][3]);
                }
            // a1 x b2
#pragma unroll
            for (int mt = 0; mt < 4; mt++)
#pragma unroll
                for (int bt = 0; bt < 2; bt++) {
                    MMA16816(acc[mt][2 * bt],     af[mt][0], af[mt][1], af[mt][2], af[mt][3],
                             b2f[bt][0], b2f[bt][2]);
                    MMA16816(acc[mt][2 * bt + 1], af[mt][0], af[mt][1], af[mt][2], af[mt][3],
                             b2f[bt][1], b2f[bt][3]);
                }
            if (NPROD == 3) {
                // a2 x b1 (reuse af registers)
#pragma unroll
                for (int mt = 0; mt < 4; mt++) {
                    uint32_t ra = (uint32_t)((wm * 64 + mt * 16 + lrow) * 128);
                    LDSM_X4(af[mt][0], af[mt][1], af[mt][2], af[mt][3],
                            abuf + swz(ra + (32 + kk * 16 + col8) * 2));
                }
#pragma unroll
                for (int mt = 0; mt < 4; mt++)
#pragma unroll
                    for (int bt = 0; bt < 2; bt++) {
                        MMA16816(acc[mt][2 * bt],     af[mt][0], af[mt][1], af[mt][2], af[mt][3],
                                 b1f[bt][0], b1f[bt][2]);
                        MMA16816(acc[mt][2 * bt + 1], af[mt][0], af[mt][1], af[mt][2], af[mt][3],
                                 b1f[bt][1], b1f[bt][3]);
                    }
            }
        }
    }

    __device__ __forceinline__ void run(const __nv_bfloat16* A, int ldA,
                                        const __nv_bfloat16* B, int ldB) {
        load_stage(0, 0, A, ldA, B, ldB);
        CP_COMMIT();
        load_stage(1, 32, A, ldA, B, ldB);
        CP_COMMIT();
        int st = 0;
        for (int c = 0; c < 32; c++) {
            CP_WAIT(1);
            __syncthreads();
            compute(st);
            int nc = c + 2;
            int ns = st + 2; if (ns >= NSTG) ns -= NSTG;
            if (nc < 32) load_stage(ns, nc * 32, A, ldA, B, ldB);
            CP_COMMIT();
            st = (st + 1 == NSTG) ? 0 : st + 1;
        }
    }
};

// ======================= merged projection GEMM (q, k, v, r) =======================
__global__ void __launch_bounds__(256, 2) proj_gemm(
    const float* __restrict__ bias_v, const float* __restrict__ bias_u)
{
    extern __shared__ char smem[];
    const int gy = blockIdx.y;
    const int c0 = blockIdx.x * 128;
    const size_t WS = (size_t)NH * KW;

    int gid, rt;
    if      (gy < 16) { gid = 0; rt = gy; }
    else if (gy < 48) { gid = 1; rt = gy - 16; }
    else if (gy < 80) { gid = 2; rt = gy - 48; }
    else              { gid = 3; rt = gy - 80; }
    const int r0 = rt * 128;

    const __nv_bfloat16* Atile;
    if (gid == 0) {
        int b = r0 >> 10;
        Atile = g_kvs + (size_t)(b * SS + MM + (r0 & 1023)) * KW;
    } else if (gid == 3) {
        Atile = g_rs + (size_t)r0 * KW;
    } else {
        Atile = g_kvs + (size_t)r0 * KW;
    }
    const __nv_bfloat16* Btile = g_wt + (size_t)gid * WS + (size_t)c0 * KW;

    Core<3> h;
    h.init(smem);
    h.run(Atile, KW, Btile, KW);

#pragma unroll
    for (int mt = 0; mt < 4; mt++) {
        int rbase = r0 + h.wm * 64 + mt * 16 + (h.lane >> 2);
#pragma unroll
        for (int nt = 0; nt < 4; nt++) {
            int cbase = c0 + h.wn * 32 + nt * 8 + (h.lane & 3) * 2;
#pragma unroll
            for (int e = 0; e < 4; e++) {
                int r = rbase + (e >> 1) * 8;
                int c = cbase + (e & 1);
                float vv = h.acc[mt][nt][e];
                size_t o = (size_t)r * 1024 + c;
                if (gid == 0) {
                    g_qv[o] = vv + bias_v[c];
                    g_qu[o] = __float2bfloat16(vv + bias_u[c]);
                } else if (gid == 1) {
                    g_kb[o] = __float2bfloat16(vv);
                } else if (gid == 2) {
                    g_vb[o] = __float2bfloat16(vv);
                } else {
                    g_r[o] = vv;
                }
            }
        }
    }
}

// ======================= output GEMM =======================
__global__ void __launch_bounds__(256, 2) out_gemm(const float* __restrict__ bo,
                                                   float* __restrict__ out)
{
    extern __shared__ char smem[];
    const int r0 = blockIdx.y * 128, c0 = blockIdx.x * 128;
    const __nv_bfloat16* Atile = g_attnb + (size_t)r0 * NH;
    const __nv_bfloat16* Btile = g_wt + 4 * (size_t)NH * KW + (size_t)c0 * KW;

    Core<2> h;
    h.init(smem);
    h.run(Atile, NH, Btile, KW);

#pragma unroll
    for (int mt = 0; mt < 4; mt++) {
        int rbase = r0 + h.wm * 64 + mt * 16 + (h.lane >> 2);
#pragma unroll
        for (int nt = 0; nt < 4; nt++) {
            int cbase = c0 + h.wn * 32 + nt * 8 + (h.lane & 3) * 2;
#pragma unroll
            for (int e = 0; e < 4; e++) {
                int r = rbase + (e >> 1) * 8;
                int c = cbase + (e & 1);
                out[(size_t)r * 1024 + c] = h.acc[mt][nt][e] + bo[c];
            }
        }
    }
}

// ======================= fused attention =======================
__global__ void __launch_bounds__(256) att_fused(const int* __restrict__ ep_idx)
{
    extern __shared__ float sm[];
    float* qu_s = sm;
    float* qv_s = qu_s + 64 * 65;
    float* k_s  = qv_s + 64 * 65;
    float* r_s  = k_s  + 64 * 65;
    float* rm_s = r_s + 128 * 65;
    float* rs_s = rm_s + 64;
    int* qi_s = (int*)(rs_s + 64);
    int* ki_s = qi_s + 64;

    const int tid = threadIdx.x;
    const int bn = blockIdx.x;
    const int b = bn >> 4, n = bn & 15;
    const int t0 = blockIdx.y * 64;
    const int ty = tid >> 4, tx = tid & 15;
    const int qbase = ty * 4, sbase = tx * 4;

    for (int e = tid; e < 4096; e += 256) {
        int q = e >> 6, h = e & 63;
        size_t row = (size_t)(b * TT + t0 + q) * NH + n * 64 + h;
        qu_s[q * 65 + h] = __bfloat162float(g_qu[row]);
        qv_s[q * 65 + h] = g_qv[row];
    }
    if (tid < 64) qi_s[tid] = g_qi[b * TT + t0 + tid];
    __syncthreads();

    const int qlo = qi_s[0], qhi = qi_s[63];
    const int causal_max = MM + t0 + 63;

    float rmax[4], rsum[4];
#pragma unroll
    for (int i = 0; i < 4; i++) { rmax[i] = -INFINITY; rsum[i] = 0.f; }

    for (int s0 = 0; s0 < SS; s0 += 64) {
        if (s0 > causal_max) break;
        {
            int klo = g_ki[b * SS + s0];
            int khi = g_ki[b * SS + s0 + 63];
            if (khi < qlo || klo > qhi) continue;
        }
        __syncthreads();
        for (int e = tid; e < 4096; e += 256) {
            int s = e >> 6, h = e & 63;
            k_s[s * 65 + h] = __bfloat162float(g_kb[(size_t)(b * SS + s0 + s) * NH + n * 64 + h]);
        }
        const int base = s0 - t0 + (TT - 64);
        for (int e = tid; e < 8192; e += 256) {
            int j = e >> 6, h = e & 63;
            int m = base + j; m = (m > SS - 1) ? SS - 1 : m; m = (m < 0) ? 0 : m;
            r_s[j * 65 + h] = g_r[(size_t)m * NH + n * 64 + h];
        }
        if (tid < 64) {
            int s = s0 + tid;
            ki_s[tid] = (s < MM) ? ep_idx[b * MM + s] : g_qi[b * TT + (s - MM)];
        }
        __syncthreads();

        float qk[4][4], bbx[4][4];
#pragma unroll
        for (int i = 0; i < 4; i++)
#pragma unroll
            for (int j = 0; j < 4; j++) { qk[i][j] = 0.f; bbx[i][j] = 0.f; }
        const int rrow0 = sbase - qbase + 60;
#pragma unroll 4
        for (int h = 0; h < 64; h++) {
            float au[4], av[4], kk4[4], rr[7];
#pragma unroll
            for (int i = 0; i < 4; i++) {
                au[i] = qu_s[(qbase + i) * 65 + h];
                av[i] = qv_s[(qbase + i) * 65 + h];
            }
#pragma unroll
            for (int j = 0; j < 4; j++) kk4[j] = k_s[(sbase + j) * 65 + h];
#pragma unroll
            for (int d = 0; d < 7; d++) rr[d] = r_s[(rrow0 + d) * 65 + h];
#pragma unroll
            for (int i = 0; i < 4; i++)
#pragma unroll
                for (int j = 0; j < 4; j++) {
                    qk[i][j]  = fmaf(au[i], kk4[j], qk[i][j]);
                    bbx[i][j] = fmaf(av[i], rr[j - i + 3], bbx[i][j]);
                }
        }
        float lv[4][4];
#pragma unroll
        for (int i = 0; i < 4; i++) {
            int tg = t0 + qbase + i;
#pragma unroll
            for (int j = 0; j < 4; j++) {
                int sg = s0 + sbase + j;
                float l = __bfloat162float(__float2bfloat16(qk[i][j])) * SCALE + bbx[i][j] * SCALE;
                bool ok = (sg <= MM + tg) && (qi_s[qbase + i] == ki_s[sbase + j]);
                l = ok ? l : NEGINF;
                lv[i][j] = l;
                g_logits[((size_t)bn * TT + tg) * SS + sg] = l;
            }
        }
#pragma unroll
        for (int i = 0; i < 4; i++) {
            float tm = fmaxf(fmaxf(lv[i][0], lv[i][1]), fmaxf(lv[i][2], lv[i][3]));
#pragma unroll
            for (int msk = 1; msk < 16; msk <<= 1)
                tm = fmaxf(tm, __shfl_xor_sync(0xffffffffu, tm, msk));
            float nm = fmaxf(rmax[i], tm);
            float ps = expf(lv[i][0] - nm) + expf(lv[i][1] - nm) +
                       expf(lv[i][2] - nm) + expf(lv[i][3] - nm);
#pragma unroll
            for (int msk = 1; msk < 16; msk <<= 1)
                ps += __shfl_xor_sync(0xffffffffu, ps, msk);
            rsum[i] = rsum[i] * expf(rmax[i] - nm) + ps;
            rmax[i] = nm;
        }
    }
    if (tx == 0) {
#pragma unroll
        for (int i = 0; i < 4; i++) {
            rm_s[qbase + i] = rmax[i];
            rs_s[qbase + i] = rsum[i];
        }
    }
    __syncthreads();

    float* p_s = qu_s;
    float* v_s = qv_s;
    float acc[4][4];
#pragma unroll
    for (int i = 0; i < 4; i++)
#pragma unroll
        for (int j = 0; j < 4; j++) acc[i][j] = 0.f;

    for (int s0 = 0; s0 < SS; s0 += 64) {
        if (s0 > causal_max) break;
        {
            int klo = g_ki[b * SS + s0];
            int khi = g_ki[b * SS + s0 + 63];
            if (khi < qlo || klo > qhi) continue;
        }
        __syncthreads();
        for (int e = tid; e < 4096; e += 256) {
            int q = e >> 6, s = e & 63;
            float L = g_logits[((size_t)bn * TT + t0 + q) * SS + s0 + s];
            float p = expf(L - rm_s[q]) / rs_s[q];
            p_s[q * 65 + s] = __bfloat162float(__float2bfloat16(p));
        }
        for (int e = tid; e < 4096; e += 256) {
            int s = e >> 6, h = e & 63;
            v_s[s * 65 + h] = __bfloat162float(g_vb[(size_t)(b * SS + s0 + s) * NH + n * 64 + h]);
        }
        __syncthreads();
#pragma unroll 8
        for (int s = 0; s < 64; s++) {
            float pv[4], vv[4];
#pragma unroll
            for (int i = 0; i < 4; i++) pv[i] = p_s[(ty * 4 + i) * 65 + s];
#pragma unroll
            for (int j = 0; j < 4; j++) vv[j] = v_s[s * 65 + tx * 4 + j];
#pragma unroll
            for (int i = 0; i < 4; i++)
#pragma unroll
                for (int j = 0; j < 4; j++)
                    acc[i][j] = fmaf(pv[i], vv[j], acc[i][j]);
        }
    }
#pragma unroll
    for (int i = 0; i < 4; i++) {
        int t = t0 + ty * 4 + i;
#pragma unroll
        for (int j = 0; j < 4; j++) {
            g_attnb[(size_t)(b * TT + t) * NH + n * 64 + tx * 4 + j] =
                __float2bfloat16(acc[i][j]);
        }
    }
}

// ======================= launch =======================
extern "C" void kernel_launch(void* const* d_in, const int* in_sizes, int n_in,
                              void* d_out, int out_size)
{
    const float* x    = (const float*)d_in[0];
    const float* rel  = (const float*)d_in[1];
    const float* mem  = (const float*)d_in[2];
    const int*   ep   = (const int*)d_in[3];
    const int*   dones= (const int*)d_in[4];
    const float* Wq   = (const float*)d_in[5];
    const float* Wk   = (const float*)d_in[6];
    const float* Wv   = (const float*)d_in[7];
    const float* Wr   = (const float*)d_in[8];
    const float* u    = (const float*)d_in[9];
    const float* v    = (const float*)d_in[10];
    const float* Wout = (const float*)d_in[11];
    const float* bo   = (const float*)d_in[12];
    float* out = (float*)d_out;
    (void)in_sizes; (void)n_in; (void)out_size;

    prep<<<PREP_GRID, 256>>>(x, mem, rel, Wq, Wk, Wv, Wr, Wout, ep, dones);

    cudaFuncSetAttribute(proj_gemm, cudaFuncAttributeMaxDynamicSharedMemorySize, CORE_SMEM);
    proj_gemm<<<dim3(8, 96), 256, CORE_SMEM>>>(v, u);

    const int att_smem = (3 * 64 * 65 + 128 * 65 + 128) * (int)sizeof(float) + 128 * (int)sizeof(int);
    cudaFuncSetAttribute(att_fused, cudaFuncAttributeMaxDynamicSharedMemorySize, att_smem);
    att_fused<<<dim3(BB * NHEAD, TT / 64), 256, att_smem>>>(ep);

    cudaFuncSetAttribute(out_gemm, cudaFuncAttributeMaxDynamicSharedMemorySize, CORE_SMEM);
    out_gemm<<<dim3(8, 16), 256, CORE_SMEM>>>(bo, out);
}

// round 15
// speedup vs baseline: 1.0035x; 1.0002x over previous
#include <cuda_runtime.h>
#include <cuda_bf16.h>
#include <cstdint>
#include <math.h>

#define BB 2
#define TT 1024
#define MM 1024
#define FF 1024
#define NHEAD 16
#define HH 64
#define SS 2048            // M + T
#define NH 1024            // N * H
#define SCALE 0.125f       // 1/sqrt(64)
#define NEGINF -1e30f

#define KW 2048            // storage width of split operands [p1|p2]
#define NCH_P 48           // logical K chunks (64 each) for projections (3x1024)
#define NCH_O 32           // logical K chunks for output gemm (2x1024)

// ======================= scratch (device globals) =======================
__device__ float         g_qv[(size_t)BB * TT * NH];
__device__ __nv_bfloat16 g_qu[(size_t)BB * TT * NH];
__device__ __nv_bfloat16 g_kb[(size_t)BB * SS * NH];
__device__ __nv_bfloat16 g_vb[(size_t)BB * SS * NH];
__device__ float         g_r [(size_t)SS * NH];
__device__ float         g_logits[(size_t)BB * NHEAD * TT * SS];
__device__ int           g_qi[BB * TT];
__device__ int           g_ki[BB * SS];

__device__ __nv_bfloat16 g_kvs[(size_t)BB * SS * KW];       // kv splits [4096][2048]
__device__ __nv_bfloat16 g_rs [(size_t)SS * KW];            // rel splits [2048][2048]
__device__ __nv_bfloat16 g_wt [5 * (size_t)NH * KW];        // 5 weights [n][2048]
__device__ __nv_bfloat16 g_attnb[(size_t)BB * TT * NH];     // bf16 attn

// ======================= PTX helpers =======================
__device__ __forceinline__ uint32_t smem_to_u32(const void* p) {
    uint32_t a;
    asm("{ .reg .u64 t; cvta.to.shared.u64 t, %1; cvt.u32.u64 %0, t; }" : "=r"(a) : "l"(p));
    return a;
}
__device__ __forceinline__ uint32_t swz(uint32_t byte_off) {
    return byte_off ^ ((byte_off >> 3) & 0x70u);
}
#define CP_ASYNC16(dst, src) \
    asm volatile("cp.async.cg.shared.global [%0], [%1], 16;" :: "r"(dst), "l"(src))
#define CP_COMMIT() asm volatile("cp.async.commit_group;" ::: "memory")
#define CP_WAIT(n)  asm volatile("cp.async.wait_group %0;" :: "n"(n) : "memory")
#define LDSM_X4(r0, r1, r2, r3, addr) \
    asm volatile("ldmatrix.sync.aligned.m8n8.x4.shared.b16 {%0,%1,%2,%3}, [%4];" \
        : "=r"(r0), "=r"(r1), "=r"(r2), "=r"(r3) : "r"(addr))
#define MMA16816(d, a0, a1, a2, a3, b0, b1) \
    asm volatile("mma.sync.aligned.m16n8k16.row.col.f32.bf16.bf16.f32 " \
        "{%0,%1,%2,%3}, {%4,%5,%6,%7}, {%8,%9}, {%0,%1,%2,%3};" \
        : "+f"((d)[0]), "+f"((d)[1]), "+f"((d)[2]), "+f"((d)[3]) \
        : "r"(a0), "r"(a1), "r"(a2), "r"(a3), "r"(b0), "r"(b1))

// logical chunk -> source column offset (elements)
// projections: A' = [a1|a1|a2], B' = [b1|b2|b1]; storage [p1|p2]
__device__ __forceinline__ int amap_proj(int c) {
    return (c < 32) ? ((c & 15) << 6) : (1024 + ((c - 32) << 6));
}
__device__ __forceinline__ int bmap_proj(int c) {
    return (c < 16) ? (c << 6) : ((c < 32) ? (1024 + ((c - 16) << 6)) : ((c - 32) << 6));
}
// output gemm: A' = [attn|attn] (storage 1024 wide), B' = [b1|b2]
__device__ __forceinline__ int amap_out(int c) { return (c & 15) << 6; }
__device__ __forceinline__ int bmap_out(int c) {
    return (c < 16) ? (c << 6) : (1024 + ((c - 16) << 6));
}

// ======================= prep kernels (split so proj_gemm is launch #4) =======================
__global__ void __launch_bounds__(256) prep_kv(const float* __restrict__ x,
                                               const float* __restrict__ mem)
{
    int g = blockIdx.x;            // 4096 rows
    int b = g >> 11, s = g & 2047;
    int f = threadIdx.x * 4;
    const float* src = (s < MM) ? (mem + ((size_t)(b * MM + s)) * FF + f)
                                : (x + ((size_t)(b * TT + (s - MM))) * FF + f);
    float4 a = *(const float4*)src;
    __nv_bfloat16 h1[4], h2[4];
    float av[4] = { a.x, a.y, a.z, a.w };
#pragma unroll
    for (int j = 0; j < 4; j++) {
        h1[j] = __float2bfloat16(av[j]);
        h2[j] = __float2bfloat16(av[j] - __bfloat162float(h1[j]));
    }
    size_t o = (size_t)g * KW + f;
    *(uint2*)&g_kvs[o] = *(uint2*)h1;
    *(uint2*)&g_kvs[o + 1024] = *(uint2*)h2;
}

__global__ void __launch_bounds__(256) prep_rel(const float* __restrict__ rel)
{
    int r = blockIdx.x;            // 2048 rows
    int f = threadIdx.x * 4;
    float4 a = *(const float4*)(rel + (size_t)r * FF + f);
    __nv_bfloat16 h1[4], h2[4];
    float av[4] = { a.x, a.y, a.z, a.w };
#pragma unroll
    for (int j = 0; j < 4; j++) {
        h1[j] = __float2bfloat16(av[j]);
        h2[j] = __float2bfloat16(av[j] - __bfloat162float(h1[j]));
    }
    size_t o = (size_t)r * KW + f;
    *(uint2*)&g_rs[o] = *(uint2*)h1;
    *(uint2*)&g_rs[o + 1024] = *(uint2*)h2;
}

// weights transpose+split (5120 blocks) + qi scan (2 blocks)
__global__ void __launch_bounds__(256) prep_wq(
    const float* __restrict__ W0, const float* __restrict__ W1, const float* __restrict__ W2,
    const float* __restrict__ W3, const float* __restrict__ W4,
    const int* __restrict__ ep, const int* __restrict__ dones)
{
    __shared__ float tsm[32][33];
    __shared__ int   sb[256];
    const int g = blockIdx.x;
    const int tid = threadIdx.x;

    if (g < 5120) {
        int w = g >> 10, tile = g & 1023;
        int bx = tile & 31, by = tile >> 5;
        const float* Ws[5] = { W0, W1, W2, W3, W4 };
        const float* W = Ws[w];
        __nv_bfloat16* o = g_wt + (size_t)w * NH * KW;
#pragma unroll
        for (int i = 0; i < 4; i++) {
            int idx = tid + i * 256;
            int ky = idx >> 5, nx = idx & 31;
            tsm[ky][nx] = W[(size_t)(by * 32 + ky) * 1024 + bx * 32 + nx];
        }
        __syncthreads();
#pragma unroll
        for (int i = 0; i < 4; i++) {
            int idx = tid + i * 256;
            int nl = idx >> 5, kl = idx & 31;
            float a = tsm[kl][nl];
            __nv_bfloat16 h1 = __float2bfloat16(a);
            __nv_bfloat16 h2 = __float2bfloat16(a - __bfloat162float(h1));
            size_t ob = (size_t)(bx * 32 + nl) * KW + by * 32 + kl;
            o[ob] = h1; o[ob + 1024] = h2;
        }
    } else {
        int b = g - 5120;
        int t4 = tid * 4;
        int d0 = dones[b * TT + t4], d1 = dones[b * TT + t4 + 1];
        int d2 = dones[b * TT + t4 + 2], d3 = dones[b * TT + t4 + 3];
        int l0 = d0, l1 = l0 + d1, l2 = l1 + d2, l3 = l2 + d3;
        sb[tid] = l3;
        __syncthreads();
        for (int off = 1; off < 256; off <<= 1) {
            int add = (tid >= off) ? sb[tid - off] : 0;
            __syncthreads();
            sb[tid] += add;
            __syncthreads();
        }
        int excl = sb[tid] - l3;
        int base = ep[b * MM + (MM - 1)];
        int q[4] = { base + excl + l0, base + excl + l1, base + excl + l2, base + excl + l3 };
#pragma unroll
        for (int j = 0; j < 4; j++) {
            g_qi[b * TT + t4 + j] = q[j];
            g_ki[b * SS + MM + t4 + j] = q[j];
            g_ki[b * SS + t4 + j] = ep[b * MM + t4 + j];
        }
    }
}

// ======================= HMMA core (R7 design), templated on A-tile rows =======================
// MROWS=128: warp tile 64x32 (mt=4); MROWS=64: warp tile 32x32 (mt=2).
// 3-stage cp.async pipeline, single K=64-chunk map per MODE.
#define NSTG 3

template <int MROWS, int MODE>
struct Core {
    static constexpr int MT = MROWS / 32;               // m-subtiles per warp
    static constexpr int ASTAGE = MROWS * 128;          // bytes
    static constexpr int BSTAGE = 16384;
    static constexpr int STAGE = ASTAGE + BSTAGE;
    static constexpr int NCH = (MODE == 0) ? NCH_P : NCH_O;

    uint32_t sbase;
    int tid, lane, wm, wn, lrow;
    uint32_t col8;
    float acc[MT][4][4];

    __device__ __forceinline__ void init(char* smem) {
        sbase = smem_to_u32(smem);
        tid = threadIdx.x; lane = tid & 31;
        int warp = tid >> 5;
        wm = warp >> 2; wn = warp & 3;
        lrow = lane & 15; col8 = (lane >> 4) * 8;
#pragma unroll
        for (int mt = 0; mt < MT; mt++)
#pragma unroll
            for (int nt = 0; nt < 4; nt++)
#pragma unroll
                for (int e = 0; e < 4; e++) acc[mt][nt][e] = 0.f;
    }
    __device__ __forceinline__ void load_stage(int stage, int ka, int kb,
            const __nv_bfloat16* __restrict__ A, int ldA,
            const __nv_bfloat16* __restrict__ B, int ldB) {
        uint32_t ab = sbase + stage * STAGE;
        uint32_t bb = ab + ASTAGE;
        const int NA = MROWS * 8;                        // cp.async count for A
#pragma unroll
        for (int it = 0; it < (MROWS + 128) / 32; it++) {
            int idx = tid + it * 256;
            if (idx < NA) {
                int row = idx >> 3, seg = idx & 7;
                CP_ASYNC16(ab + swz((uint32_t)(row * 128 + seg * 16)),
                           A + (size_t)row * ldA + ka + seg * 8);
            } else {
                int r2 = idx - NA;
                int row = r2 >> 3, seg = r2 & 7;
                CP_ASYNC16(bb + swz((uint32_t)(row * 128 + seg * 16)),
                           B + (size_t)row * ldB + kb + seg * 8);
            }
        }
    }
    __device__ __forceinline__ void compute(int stage) {
        uint32_t ab = sbase + stage * STAGE;
        uint32_t bb = ab + ASTAGE;
#pragma unroll
        for (int kk = 0; kk < 4; kk++) {
            uint32_t bfr[2][4];
#pragma unroll
            for (int bt = 0; bt < 2; bt++) {
                uint32_t addr = bb + swz((uint32_t)((wn * 32 + bt * 16 + lrow) * 128 +
                                                    (kk * 16 + col8) * 2));
                LDSM_X4(bfr[bt][0], bfr[bt][1], bfr[bt][2], bfr[bt][3], addr);
            }
#pragma unroll
            for (int mt = 0; mt < MT; mt++) {
                uint32_t a0, a1, a2, a3;
                uint32_t addr = ab + swz((uint32_t)((wm * (MROWS / 2) + mt * 16 + lrow) * 128 +
                                                    (kk * 16 + col8) * 2));
                LDSM_X4(a0, a1, a2, a3, addr);
#pragma unroll
                for (int bt = 0; bt < 2; bt++) {
                    MMA16816(acc[mt][2 * bt],     a0, a1, a2, a3, bfr[bt][0], bfr[bt][2]);
                    MMA16816(acc[mt][2 * bt + 1], a0, a1, a2, a3, bfr[bt][1], bfr[bt][3]);
                }
            }
        }
    }
    __device__ __forceinline__ void run(const __nv_bfloat16* A, int ldA,
                                        const __nv_bfloat16* B, int ldB) {
        auto am = [](int c) { return (MODE == 0) ? amap_proj(c) : amap_out(c); };
        auto bm = [](int c) { return (MODE == 0) ? bmap_proj(c) : bmap_out(c); };
        load_stage(0, am(0), bm(0), A, ldA, B, ldB);
        CP_COMMIT();
        load_stage(1, am(1), bm(1), A, ldA, B, ldB);
        CP_COMMIT();
        int st = 0;
        for (int c = 0; c < NCH; c++) {
            CP_WAIT(1);
            __syncthreads();
            compute(st);
            int nc = c + 2;
            int ns = st + 2; if (ns >= NSTG) ns -= NSTG;
            if (nc < NCH) load_stage(ns, am(nc), bm(nc), A, ldA, B, ldB);
            CP_COMMIT();
            st = (st + 1 == NSTG) ? 0 : st + 1;
        }
    }
};

#define PJ_SMEM (NSTG * (128 * 128 + 16384))   // 96 KB
#define PO_SMEM (NSTG * (64 * 128 + 16384))    // 72 KB

// ======================= merged projection GEMM (q, k, v, r) =======================
__global__ void __launch_bounds__(256, 2) proj_gemm(
    const float* __restrict__ bias_v, const float* __restrict__ bias_u)
{
    extern __shared__ char smem[];
    const int gy = blockIdx.y;
    const int c0 = blockIdx.x * 128;
    const size_t WS = (size_t)NH * KW;

    int gid, rt;
    if      (gy < 16) { gid = 0; rt = gy; }
    else if (gy < 48) { gid = 1; rt = gy - 16; }
    else if (gy < 80) { gid = 2; rt = gy - 48; }
    else              { gid = 3; rt = gy - 80; }
    const int r0 = rt * 128;

    const __nv_bfloat16* Atile;
    if (gid == 0) {
        int b = r0 >> 10;
        Atile = g_kvs + (size_t)(b * SS + MM + (r0 & 1023)) * KW;
    } else if (gid == 3) {
        Atile = g_rs + (size_t)r0 * KW;
    } else {
        Atile = g_kvs + (size_t)r0 * KW;
    }
    const __nv_bfloat16* Btile = g_wt + (size_t)gid * WS + (size_t)c0 * KW;

    Core<128, 0> h;
    h.init(smem);
    h.run(Atile, KW, Btile, KW);

#pragma unroll
    for (int mt = 0; mt < 4; mt++) {
        int rbase = r0 + h.wm * 64 + mt * 16 + (h.lane >> 2);
#pragma unroll
        for (int nt = 0; nt < 4; nt++) {
            int cbase = c0 + h.wn * 32 + nt * 8 + (h.lane & 3) * 2;
#pragma unroll
            for (int e = 0; e < 4; e++) {
                int r = rbase + (e >> 1) * 8;
                int c = cbase + (e & 1);
                float vv = h.acc[mt][nt][e];
                size_t o = (size_t)r * 1024 + c;
                if (gid == 0) {
                    g_qv[o] = vv + bias_v[c];
                    g_qu[o] = __float2bfloat16(vv + bias_u[c]);
                } else if (gid == 1) {
                    g_kb[o] = __float2bfloat16(vv);
                } else if (gid == 2) {
                    g_vb[o] = __float2bfloat16(vv);
                } else {
                    g_r[o] = vv;
                }
            }
        }
    }
}

// ======================= output GEMM (64x128 tiles -> 256 CTAs, 2/SM) =======================
__global__ void __launch_bounds__(256, 2) out_gemm(const float* __restrict__ bo,
                                                   float* __restrict__ out)
{
    extern __shared__ char smem[];
    const int r0 = blockIdx.y * 64, c0 = blockIdx.x * 128;
    const __nv_bfloat16* Atile = g_attnb + (size_t)r0 * NH;
    const __nv_bfloat16* Btile = g_wt + 4 * (size_t)NH * KW + (size_t)c0 * KW;

    Core<64, 1> h;
    h.init(smem);
    h.run(Atile, NH, Btile, KW);

#pragma unroll
    for (int mt = 0; mt < 2; mt++) {
        int rbase = r0 + h.wm * 32 + mt * 16 + (h.lane >> 2);
#pragma unroll
        for (int nt = 0; nt < 4; nt++) {
            int cbase = c0 + h.wn * 32 + nt * 8 + (h.lane & 3) * 2;
#pragma unroll
            for (int e = 0; e < 4; e++) {
                int r = rbase + (e >> 1) * 8;
                int c = cbase + (e & 1);
                out[(size_t)r * 1024 + c] = h.acc[mt][nt][e] + bo[c];
            }
        }
    }
}

// ======================= fused attention =======================
__global__ void __launch_bounds__(256) att_fused(const int* __restrict__ ep_idx)
{
    extern __shared__ float sm[];
    float* qu_s = sm;
    float* qv_s = qu_s + 64 * 65;
    float* k_s  = qv_s + 64 * 65;
    float* r_s  = k_s  + 64 * 65;
    float* rm_s = r_s + 128 * 65;
    float* rs_s = rm_s + 64;
    int* qi_s = (int*)(rs_s + 64);
    int* ki_s = qi_s + 64;

    const int tid = threadIdx.x;
    const int bn = blockIdx.x;
    const int b = bn >> 4, n = bn & 15;
    const int t0 = blockIdx.y * 64;
    const int ty = tid >> 4, tx = tid & 15;
    const int qbase = ty * 4, sbase = tx * 4;

    for (int e = tid; e < 4096; e += 256) {
        int q = e >> 6, h = e & 63;
        size_t row = (size_t)(b * TT + t0 + q) * NH + n * 64 + h;
        qu_s[q * 65 + h] = __bfloat162float(g_qu[row]);
        qv_s[q * 65 + h] = g_qv[row];
    }
    if (tid < 64) qi_s[tid] = g_qi[b * TT + t0 + tid];
    __syncthreads();

    const int qlo = qi_s[0], qhi = qi_s[63];
    const int causal_max = MM + t0 + 63;

    float rmax[4], rsum[4];
#pragma unroll
    for (int i = 0; i < 4; i++) { rmax[i] = -INFINITY; rsum[i] = 0.f; }

    for (int s0 = 0; s0 < SS; s0 += 64) {
        if (s0 > causal_max) break;
        {
            int klo = g_ki[b * SS + s0];
            int khi = g_ki[b * SS + s0 + 63];
            if (khi < qlo || klo > qhi) continue;
        }
        __syncthreads();
        for (int e = tid; e < 4096; e += 256) {
            int s = e >> 6, h = e & 63;
            k_s[s * 65 + h] = __bfloat162float(g_kb[(size_t)(b * SS + s0 + s) * NH + n * 64 + h]);
        }
        const int base = s0 - t0 + (TT - 64);
        for (int e = tid; e < 8192; e += 256) {
            int j = e >> 6, h = e & 63;
            int m = base + j; m = (m > SS - 1) ? SS - 1 : m; m = (m < 0) ? 0 : m;
            r_s[j * 65 + h] = g_r[(size_t)m * NH + n * 64 + h];
        }
        if (tid < 64) {
            int s = s0 + tid;
            ki_s[tid] = (s < MM) ? ep_idx[b * MM + s] : g_qi[b * TT + (s - MM)];
        }
        __syncthreads();

        float qk[4][4], bbx[4][4];
#pragma unroll
        for (int i = 0; i < 4; i++)
#pragma unroll
            for (int j = 0; j < 4; j++) { qk[i][j] = 0.f; bbx[i][j] = 0.f; }
        const int rrow0 = sbase - qbase + 60;
#pragma unroll 4
        for (int h = 0; h < 64; h++) {
            float au[4], av[4], kk4[4], rr[7];
#pragma unroll
            for (int i = 0; i < 4; i++) {
                au[i] = qu_s[(qbase + i) * 65 + h];
                av[i] = qv_s[(qbase + i) * 65 + h];
            }
#pragma unroll
            for (int j = 0; j < 4; j++) kk4[j] = k_s[(sbase + j) * 65 + h];
#pragma unroll
            for (int d = 0; d < 7; d++) rr[d] = r_s[(rrow0 + d) * 65 + h];
#pragma unroll
            for (int i = 0; i < 4; i++)
#pragma unroll
                for (int j = 0; j < 4; j++) {
                    qk[i][j]  = fmaf(au[i], kk4[j], qk[i][j]);
                    bbx[i][j] = fmaf(av[i], rr[j - i + 3], bbx[i][j]);
                }
        }
        float lv[4][4];
#pragma unroll
        for (int i = 0; i < 4; i++) {
            int tg = t0 + qbase + i;
#pragma unroll
            for (int j = 0; j < 4; j++) {
                int sg = s0 + sbase + j;
                float l = __bfloat162float(__float2bfloat16(qk[i][j])) * SCALE + bbx[i][j] * SCALE;
                bool ok = (sg <= MM + tg) && (qi_s[qbase + i] == ki_s[sbase + j]);
                l = ok ? l : NEGINF;
                lv[i][j] = l;
                g_logits[((size_t)bn * TT + tg) * SS + sg] = l;
            }
        }
#pragma unroll
        for (int i = 0; i < 4; i++) {
            float tm = fmaxf(fmaxf(lv[i][0], lv[i][1]), fmaxf(lv[i][2], lv[i][3]));
#pragma unroll
            for (int msk = 1; msk < 16; msk <<= 1)
                tm = fmaxf(tm, __shfl_xor_sync(0xffffffffu, tm, msk));
            float nm = fmaxf(rmax[i], tm);
            float ps = expf(lv[i][0] - nm) + expf(lv[i][1] - nm) +
                       expf(lv[i][2] - nm) + expf(lv[i][3] - nm);
#pragma unroll
            for (int msk = 1; msk < 16; msk <<= 1)
                ps += __shfl_xor_sync(0xffffffffu, ps, msk);
            rsum[i] = rsum[i] * expf(rmax[i] - nm) + ps;
            rmax[i] = nm;
        }
    }
    if (tx == 0) {
#pragma unroll
        for (int i = 0; i < 4; i++) {
            rm_s[qbase + i] = rmax[i];
            rs_s[qbase + i] = rsum[i];
        }
    }
    __syncthreads();

    float* p_s = qu_s;
    float* v_s = qv_s;
    float acc[4][4];
#pragma unroll
    for (int i = 0; i < 4; i++)
#pragma unroll
        for (int j = 0; j < 4; j++) acc[i][j] = 0.f;

    for (int s0 = 0; s0 < SS; s0 += 64) {
        if (s0 > causal_max) break;
        {
            int klo = g_ki[b * SS + s0];
            int khi = g_ki[b * SS + s0 + 63];
            if (khi < qlo || klo > qhi) continue;
        }
        __syncthreads();
        for (int e = tid; e < 4096; e += 256) {
            int q = e >> 6, s = e & 63;
            float L = g_logits[((size_t)bn * TT + t0 + q) * SS + s0 + s];
            float p = expf(L - rm_s[q]) / rs_s[q];
            p_s[q * 65 + s] = __bfloat162float(__float2bfloat16(p));
        }
        for (int e = tid; e < 4096; e += 256) {
            int s = e >> 6, h = e & 63;
            v_s[s * 65 + h] = __bfloat162float(g_vb[(size_t)(b * SS + s0 + s) * NH + n * 64 + h]);
        }
        __syncthreads();
#pragma unroll 8
        for (int s = 0; s < 64; s++) {
            float pv[4], vv[4];
#pragma unroll
            for (int i = 0; i < 4; i++) pv[i] = p_s[(ty * 4 + i) * 65 + s];
#pragma unroll
            for (int j = 0; j < 4; j++) vv[j] = v_s[s * 65 + tx * 4 + j];
#pragma unroll
            for (int i = 0; i < 4; i++)
#pragma unroll
                for (int j = 0; j < 4; j++)
                    acc[i][j] = fmaf(pv[i], vv[j], acc[i][j]);
        }
    }
#pragma unroll
    for (int i = 0; i < 4; i++) {
        int t = t0 + ty * 4 + i;
#pragma unroll
        for (int j = 0; j < 4; j++) {
            g_attnb[(size_t)(b * TT + t) * NH + n * 64 + tx * 4 + j] =
                __float2bfloat16(acc[i][j]);
        }
    }
}

// ======================= launch =======================
extern "C" void kernel_launch(void* const* d_in, const int* in_sizes, int n_in,
                              void* d_out, int out_size)
{
    const float* x    = (const float*)d_in[0];
    const float* rel  = (const float*)d_in[1];
    const float* mem  = (const float*)d_in[2];
    const int*   ep   = (const int*)d_in[3];
    const int*   dones= (const int*)d_in[4];
    const float* Wq   = (const float*)d_in[5];
    const float* Wk   = (const float*)d_in[6];
    const float* Wv   = (const float*)d_in[7];
    const float* Wr   = (const float*)d_in[8];
    const float* u    = (const float*)d_in[9];
    const float* v    = (const float*)d_in[10];
    const float* Wout = (const float*)d_in[11];
    const float* bo   = (const float*)d_in[12];
    float* out = (float*)d_out;
    (void)in_sizes; (void)n_in; (void)out_size;

    // launches #1..#3 (so proj_gemm is launch #4 for the profiler)
    prep_kv<<<BB * SS, 256>>>(x, mem);
    prep_rel<<<SS, 256>>>(rel);
    prep_wq<<<5122, 256>>>(Wq, Wk, Wv, Wr, Wout, ep, dones);

    // launch #4: the kernel we need profiled
    cudaFuncSetAttribute(proj_gemm, cudaFuncAttributeMaxDynamicSharedMemorySize, PJ_SMEM);
    proj_gemm<<<dim3(8, 96), 256, PJ_SMEM>>>(v, u);

    const int att_smem = (3 * 64 * 65 + 128 * 65 + 128) * (int)sizeof(float) + 128 * (int)sizeof(int);
    cudaFuncSetAttribute(att_fused, cudaFuncAttributeMaxDynamicSharedMemorySize, att_smem);
    att_fused<<<dim3(BB * NHEAD, TT / 64), 256, att_smem>>>(ep);

    cudaFuncSetAttribute(out_gemm, cudaFuncAttributeMaxDynamicSharedMemorySize, PO_SMEM);
    out_gemm<<<dim3(8, 32), 256, PO_SMEM>>>(bo, out);
}

// round 17
// speedup vs baseline: 1.0353x; 1.0316x over previous
#include <cuda_runtime.h>
#include <cuda_bf16.h>
#include <cstdint>
#include <math.h>

#define BB 2
#define TT 1024
#define MM 1024
#define FF 1024
#define NHEAD 16
#define HH 64
#define SS 2048            // M + T
#define NH 1024            // N * H
#define SCALE 0.125f       // 1/sqrt(64)
#define NEGINF -1e30f

#define KW 2048            // storage width of split operands [p1|p2]
#define NCH_P 48
#define NCH_O 32

// ======================= scratch (device globals) =======================
__device__ float         g_qv[(size_t)BB * TT * NH];
__device__ __nv_bfloat16 g_qu[(size_t)BB * TT * NH];
__device__ __nv_bfloat16 g_kb[(size_t)BB * SS * NH];
__device__ __nv_bfloat16 g_vb[(size_t)BB * SS * NH];
__device__ float         g_r [(size_t)SS * NH];
__device__ float         g_logits[(size_t)BB * NHEAD * TT * SS];
__device__ int           g_qi[BB * TT];
__device__ int           g_ki[BB * SS];

__device__ __nv_bfloat16 g_kvs[(size_t)BB * SS * KW];
__device__ __nv_bfloat16 g_rs [(size_t)SS * KW];
__device__ __nv_bfloat16 g_wt [5 * (size_t)NH * KW];
__device__ __nv_bfloat16 g_attnb[(size_t)BB * TT * NH];

// ======================= PTX helpers =======================
__device__ __forceinline__ uint32_t smem_to_u32(const void* p) {
    uint32_t a;
    asm("{ .reg .u64 t; cvta.to.shared.u64 t, %1; cvt.u32.u64 %0, t; }" : "=r"(a) : "l"(p));
    return a;
}
__device__ __forceinline__ uint32_t swz(uint32_t byte_off) {
    return byte_off ^ ((byte_off >> 3) & 0x70u);
}
#define CP_ASYNC16(dst, src) \
    asm volatile("cp.async.cg.shared.global [%0], [%1], 16;" :: "r"(dst), "l"(src))
#define CP_COMMIT() asm volatile("cp.async.commit_group;" ::: "memory")
#define CP_WAIT(n)  asm volatile("cp.async.wait_group %0;" :: "n"(n) : "memory")
#define LDSM_X4(r0, r1, r2, r3, addr) \
    asm volatile("ldmatrix.sync.aligned.m8n8.x4.shared.b16 {%0,%1,%2,%3}, [%4];" \
        : "=r"(r0), "=r"(r1), "=r"(r2), "=r"(r3) : "r"(addr))
#define MMA16816(d, a0, a1, a2, a3, b0, b1) \
    asm volatile("mma.sync.aligned.m16n8k16.row.col.f32.bf16.bf16.f32 " \
        "{%0,%1,%2,%3}, {%4,%5,%6,%7}, {%8,%9}, {%0,%1,%2,%3};" \
        : "+f"((d)[0]), "+f"((d)[1]), "+f"((d)[2]), "+f"((d)[3]) \
        : "r"(a0), "r"(a1), "r"(a2), "r"(a3), "r"(b0), "r"(b1))

// chunk -> source column maps
__device__ __forceinline__ int amap_proj(int c) {
    return (c < 32) ? ((c & 15) << 6) : (1024 + ((c - 32) << 6));
}
__device__ __forceinline__ int bmap_proj(int c) {
    return (c < 16) ? (c << 6) : ((c < 32) ? (1024 + ((c - 16) << 6)) : ((c - 32) << 6));
}
__device__ __forceinline__ int amap_out(int c) { return (c & 15) << 6; }
__device__ __forceinline__ int bmap_out(int c) {
    return (c < 16) ? (c << 6) : (1024 + ((c - 16) << 6));
}

// ======================= prep kernels =======================
__global__ void __launch_bounds__(256) prep_kv(const float* __restrict__ x,
                                               const float* __restrict__ mem)
{
    int g = blockIdx.x;
    int b = g >> 11, s = g & 2047;
    int f = threadIdx.x * 4;
    const float* src = (s < MM) ? (mem + ((size_t)(b * MM + s)) * FF + f)
                                : (x + ((size_t)(b * TT + (s - MM))) * FF + f);
    float4 a = *(const float4*)src;
    __nv_bfloat16 h1[4], h2[4];
    float av[4] = { a.x, a.y, a.z, a.w };
#pragma unroll
    for (int j = 0; j < 4; j++) {
        h1[j] = __float2bfloat16(av[j]);
        h2[j] = __float2bfloat16(av[j] - __bfloat162float(h1[j]));
    }
    size_t o = (size_t)g * KW + f;
    *(uint2*)&g_kvs[o] = *(uint2*)h1;
    *(uint2*)&g_kvs[o + 1024] = *(uint2*)h2;
}

// rel split (2048) + weight transpose/split (5120) + qi scan (2)
__global__ void __launch_bounds__(256) prep_rest(
    const float* __restrict__ rel,
    const float* __restrict__ W0, const float* __restrict__ W1, const float* __restrict__ W2,
    const float* __restrict__ W3, const float* __restrict__ W4,
    const int* __restrict__ ep, const int* __restrict__ dones)
{
    __shared__ float tsm[32][33];
    __shared__ int   sb[256];
    const int g = blockIdx.x;
    const int tid = threadIdx.x;

    if (g < 2048) {
        int r = g;
        int f = tid * 4;
        float4 a = *(const float4*)(rel + (size_t)r * FF + f);
        __nv_bfloat16 h1[4], h2[4];
        float av[4] = { a.x, a.y, a.z, a.w };
#pragma unroll
        for (int j = 0; j < 4; j++) {
            h1[j] = __float2bfloat16(av[j]);
            h2[j] = __float2bfloat16(av[j] - __bfloat162float(h1[j]));
        }
        size_t o = (size_t)r * KW + f;
        *(uint2*)&g_rs[o] = *(uint2*)h1;
        *(uint2*)&g_rs[o + 1024] = *(uint2*)h2;
    } else if (g < 2048 + 5120) {
        int tt = g - 2048;
        int w = tt >> 10, tile = tt & 1023;
        int bx = tile & 31, by = tile >> 5;
        const float* Ws[5] = { W0, W1, W2, W3, W4 };
        const float* W = Ws[w];
        __nv_bfloat16* o = g_wt + (size_t)w * NH * KW;
#pragma unroll
        for (int i = 0; i < 4; i++) {
            int idx = tid + i * 256;
            int ky = idx >> 5, nx = idx & 31;
            tsm[ky][nx] = W[(size_t)(by * 32 + ky) * 1024 + bx * 32 + nx];
        }
        __syncthreads();
#pragma unroll
        for (int i = 0; i < 4; i++) {
            int idx = tid + i * 256;
            int nl = idx >> 5, kl = idx & 31;
            float a = tsm[kl][nl];
            __nv_bfloat16 h1 = __float2bfloat16(a);
            __nv_bfloat16 h2 = __float2bfloat16(a - __bfloat162float(h1));
            size_t ob = (size_t)(bx * 32 + nl) * KW + by * 32 + kl;
            o[ob] = h1; o[ob + 1024] = h2;
        }
    } else {
        int b = g - (2048 + 5120);
        int t4 = tid * 4;
        int d0 = dones[b * TT + t4], d1 = dones[b * TT + t4 + 1];
        int d2 = dones[b * TT + t4 + 2], d3 = dones[b * TT + t4 + 3];
        int l0 = d0, l1 = l0 + d1, l2 = l1 + d2, l3 = l2 + d3;
        sb[tid] = l3;
        __syncthreads();
        for (int off = 1; off < 256; off <<= 1) {
            int add = (tid >= off) ? sb[tid - off] : 0;
            __syncthreads();
            sb[tid] += add;
            __syncthreads();
        }
        int excl = sb[tid] - l3;
        int base = ep[b * MM + (MM - 1)];
        int q[4] = { base + excl + l0, base + excl + l1, base + excl + l2, base + excl + l3 };
#pragma unroll
        for (int j = 0; j < 4; j++) {
            g_qi[b * TT + t4 + j] = q[j];
            g_ki[b * SS + MM + t4 + j] = q[j];
            g_ki[b * SS + t4 + j] = ep[b * MM + t4 + j];
        }
    }
}

// ======================= HMMA core (R7 design) =======================
#define NSTG 3

template <int MROWS, int MODE>
struct Core {
    static constexpr int MT = MROWS / 32;
    static constexpr int ASTAGE = MROWS * 128;
    static constexpr int BSTAGE = 16384;
    static constexpr int STAGE = ASTAGE + BSTAGE;
    static constexpr int NCH = (MODE == 0) ? NCH_P : NCH_O;

    uint32_t sbase;
    int tid, lane, wm, wn, lrow;
    uint32_t col8;
    float acc[MT][4][4];

    __device__ __forceinline__ void init(char* smem) {
        sbase = smem_to_u32(smem);
        tid = threadIdx.x; lane = tid & 31;
        int warp = tid >> 5;
        wm = warp >> 2; wn = warp & 3;
        lrow = lane & 15; col8 = (lane >> 4) * 8;
#pragma unroll
        for (int mt = 0; mt < MT; mt++)
#pragma unroll
            for (int nt = 0; nt < 4; nt++)
#pragma unroll
                for (int e = 0; e < 4; e++) acc[mt][nt][e] = 0.f;
    }
    __device__ __forceinline__ void load_stage(int stage, int ka, int kb,
            const __nv_bfloat16* __restrict__ A, int ldA,
            const __nv_bfloat16* __restrict__ B, int ldB) {
        uint32_t ab = sbase + stage * STAGE;
        uint32_t bb = ab + ASTAGE;
        const int NA = MROWS * 8;
#pragma unroll
        for (int it = 0; it < (MROWS + 128) / 32; it++) {
            int idx = tid + it * 256;
            if (idx < NA) {
                int row = idx >> 3, seg = idx & 7;
                CP_ASYNC16(ab + swz((uint32_t)(row * 128 + seg * 16)),
                           A + (size_t)row * ldA + ka + seg * 8);
            } else {
                int r2 = idx - NA;
                int row = r2 >> 3, seg = r2 & 7;
                CP_ASYNC16(bb + swz((uint32_t)(row * 128 + seg * 16)),
                           B + (size_t)row * ldB + kb + seg * 8);
            }
        }
    }
    __device__ __forceinline__ void compute(int stage) {
        uint32_t ab = sbase + stage * STAGE;
        uint32_t bb = ab + ASTAGE;
#pragma unroll
        for (int kk = 0; kk < 4; kk++) {
            uint32_t bfr[2][4];
#pragma unroll
            for (int bt = 0; bt < 2; bt++) {
                uint32_t addr = bb + swz((uint32_t)((wn * 32 + bt * 16 + lrow) * 128 +
                                                    (kk * 16 + col8) * 2));
                LDSM_X4(bfr[bt][0], bfr[bt][1], bfr[bt][2], bfr[bt][3], addr);
            }
#pragma unroll
            for (int mt = 0; mt < MT; mt++) {
                uint32_t a0, a1, a2, a3;
                uint32_t addr = ab + swz((uint32_t)((wm * (MROWS / 2) + mt * 16 + lrow) * 128 +
                                                    (kk * 16 + col8) * 2));
                LDSM_X4(a0, a1, a2, a3, addr);
#pragma unroll
                for (int bt = 0; bt < 2; bt++) {
                    MMA16816(acc[mt][2 * bt],     a0, a1, a2, a3, bfr[bt][0], bfr[bt][2]);
                    MMA16816(acc[mt][2 * bt + 1], a0, a1, a2, a3, bfr[bt][1], bfr[bt][3]);
                }
            }
        }
    }
    __device__ __forceinline__ void run(const __nv_bfloat16* A, int ldA,
                                        const __nv_bfloat16* B, int ldB) {
        auto am = [](int c) { return (MODE == 0) ? amap_proj(c) : amap_out(c); };
        auto bm = [](int c) { return (MODE == 0) ? bmap_proj(c) : bmap_out(c); };
        load_stage(0, am(0), bm(0), A, ldA, B, ldB);
        CP_COMMIT();
        load_stage(1, am(1), bm(1), A, ldA, B, ldB);
        CP_COMMIT();
        int st = 0;
        for (int c = 0; c < NCH; c++) {
            CP_WAIT(1);
            __syncthreads();
            compute(st);
            int nc = c + 2;
            int ns = st + 2; if (ns >= NSTG) ns -= NSTG;
            if (nc < NCH) load_stage(ns, am(nc), bm(nc), A, ldA, B, ldB);
            CP_COMMIT();
            st = (st + 1 == NSTG) ? 0 : st + 1;
        }
    }
};

#define PJ_SMEM (NSTG * (128 * 128 + 16384))   // 96 KB
#define PO_SMEM (NSTG * (64 * 128 + 16384))    // 72 KB

// ======================= merged projection GEMM =======================
__global__ void __launch_bounds__(256, 2) proj_gemm(
    const float* __restrict__ bias_v, const float* __restrict__ bias_u)
{
    extern __shared__ char smem[];
    const int gy = blockIdx.y;
    const int c0 = blockIdx.x * 128;
    const size_t WS = (size_t)NH * KW;

    int gid, rt;
    if      (gy < 16) { gid = 0; rt = gy; }
    else if (gy < 48) { gid = 1; rt = gy - 16; }
    else if (gy < 80) { gid = 2; rt = gy - 48; }
    else              { gid = 3; rt = gy - 80; }
    const int r0 = rt * 128;

    const __nv_bfloat16* Atile;
    if (gid == 0) {
        int b = r0 >> 10;
        Atile = g_kvs + (size_t)(b * SS + MM + (r0 & 1023)) * KW;
    } else if (gid == 3) {
        Atile = g_rs + (size_t)r0 * KW;
    } else {
        Atile = g_kvs + (size_t)r0 * KW;
    }
    const __nv_bfloat16* Btile = g_wt + (size_t)gid * WS + (size_t)c0 * KW;

    Core<128, 0> h;
    h.init(smem);
    h.run(Atile, KW, Btile, KW);

#pragma unroll
    for (int mt = 0; mt < 4; mt++) {
        int rbase = r0 + h.wm * 64 + mt * 16 + (h.lane >> 2);
#pragma unroll
        for (int nt = 0; nt < 4; nt++) {
            int cbase = c0 + h.wn * 32 + nt * 8 + (h.lane & 3) * 2;
#pragma unroll
            for (int e = 0; e < 4; e++) {
                int r = rbase + (e >> 1) * 8;
                int c = cbase + (e & 1);
                float vv = h.acc[mt][nt][e];
                size_t o = (size_t)r * 1024 + c;
                if (gid == 0) {
                    g_qv[o] = vv + bias_v[c];
                    g_qu[o] = __float2bfloat16(vv + bias_u[c]);
                } else if (gid == 1) {
                    g_kb[o] = __float2bfloat16(vv);
                } else if (gid == 2) {
                    g_vb[o] = __float2bfloat16(vv);
                } else {
                    g_r[o] = vv;
                }
            }
        }
    }
}

// ======================= output GEMM =======================
__global__ void __launch_bounds__(256, 2) out_gemm(const float* __restrict__ bo,
                                                   float* __restrict__ out)
{
    extern __shared__ char smem[];
    const int r0 = blockIdx.y * 64, c0 = blockIdx.x * 128;
    const __nv_bfloat16* Atile = g_attnb + (size_t)r0 * NH;
    const __nv_bfloat16* Btile = g_wt + 4 * (size_t)NH * KW + (size_t)c0 * KW;

    Core<64, 1> h;
    h.init(smem);
    h.run(Atile, NH, Btile, KW);

#pragma unroll
    for (int mt = 0; mt < 2; mt++) {
        int rbase = r0 + h.wm * 32 + mt * 16 + (h.lane >> 2);
#pragma unroll
        for (int nt = 0; nt < 4; nt++) {
            int cbase = c0 + h.wn * 32 + nt * 8 + (h.lane & 3) * 2;
#pragma unroll
            for (int e = 0; e < 4; e++) {
                int r = rbase + (e >> 1) * 8;
                int c = cbase + (e & 1);
                out[(size_t)r * 1024 + c] = h.acc[mt][nt][e] + bo[c];
            }
        }
    }
}

// ======================= fused attention (vectorized smem) =======================
// Layouts: qu_s/qv_s [q][h] stride 68 (float4 over h, broadcast reads)
//          k_s [h][s] stride 68 (float4 over s, bank-spread reads)
//          r_s [h][j] stride 132 (float4 over j)
// FMA order over h / s identical to scalar version -> bit-identical results.
#define QS 68
#define RS 132
#define ATT_SMEM ((3 * 64 * QS + 64 * RS + 128) * 4 + 128 * 4)

__global__ void __launch_bounds__(256) att_fused(const int* __restrict__ ep_idx)
{
    extern __shared__ float sm[];
    float* qu_s = sm;                      // 64*68  (phase2: p_s)
    float* qv_s = qu_s + 64 * QS;          // 64*68  (phase2: v_s)
    float* k_s  = qv_s + 64 * QS;          // 64*68  [h][s]
    float* r_s  = k_s  + 64 * QS;          // 64*132 [h][j]
    float* rm_s = r_s + 64 * RS;
    float* rs_s = rm_s + 64;
    int* qi_s = (int*)(rs_s + 64);
    int* ki_s = qi_s + 64;

    const int tid = threadIdx.x;
    const int bn = blockIdx.x;
    const int b = bn >> 4, n = bn & 15;
    const int t0 = blockIdx.y * 64;
    const int ty = tid >> 4, tx = tid & 15;
    const int qbase = ty * 4, sbase = tx * 4;

    for (int e = tid; e < 4096; e += 256) {
        int q = e >> 6, h = e & 63;
        size_t row = (size_t)(b * TT + t0 + q) * NH + n * 64 + h;
        qu_s[q * QS + h] = __bfloat162float(g_qu[row]);
        qv_s[q * QS + h] = g_qv[row];
    }
    if (tid < 64) qi_s[tid] = g_qi[b * TT + t0 + tid];
    __syncthreads();

    const int qlo = qi_s[0], qhi = qi_s[63];
    const int causal_max = MM + t0 + 63;

    float rmax[4], rsum[4];
#pragma unroll
    for (int i = 0; i < 4; i++) { rmax[i] = -INFINITY; rsum[i] = 0.f; }

    for (int s0 = 0; s0 < SS; s0 += 64) {
        if (s0 > causal_max) break;
        {
            int klo = g_ki[b * SS + s0];
            int khi = g_ki[b * SS + s0 + 63];
            if (khi < qlo || klo > qhi) continue;
        }
        __syncthreads();
        // k transposed fill: [h][s]
        for (int e = tid; e < 4096; e += 256) {
            int s = e >> 6, h = e & 63;
            k_s[h * QS + s] = __bfloat162float(g_kb[(size_t)(b * SS + s0 + s) * NH + n * 64 + h]);
        }
        // r transposed fill: [h][j]
        const int base = s0 - t0 + (TT - 64);
        for (int e = tid; e < 8192; e += 256) {
            int j = e >> 6, h = e & 63;
            int m = base + j; m = (m > SS - 1) ? SS - 1 : m; m = (m < 0) ? 0 : m;
            r_s[h * RS + j] = g_r[(size_t)m * NH + n * 64 + h];
        }
        if (tid < 64) {
            int s = s0 + tid;
            ki_s[tid] = (s < MM) ? ep_idx[b * MM + s] : g_qi[b * TT + (s - MM)];
        }
        __syncthreads();

        float qk[4][4], bbx[4][4];
#pragma unroll
        for (int i = 0; i < 4; i++)
#pragma unroll
            for (int j = 0; j < 4; j++) { qk[i][j] = 0.f; bbx[i][j] = 0.f; }
        const int rrow0 = sbase - qbase + 60;   // in [0,120], mult of 4

#pragma unroll 2
        for (int h4 = 0; h4 < 16; h4++) {
            float au_[4][4], av_[4][4];
#pragma unroll
            for (int i = 0; i < 4; i++) {
                *(float4*)&au_[i][0] = *(const float4*)&qu_s[(qbase + i) * QS + h4 * 4];
                *(float4*)&av_[i][0] = *(const float4*)&qv_s[(qbase + i) * QS + h4 * 4];
            }
#pragma unroll
            for (int hh = 0; hh < 4; hh++) {
                int h = h4 * 4 + hh;
                float kk_[4];
                *(float4*)&kk_[0] = *(const float4*)&k_s[h * QS + sbase];
                float rr[8];
                *(float4*)&rr[0] = *(const float4*)&r_s[h * RS + rrow0];
                *(float4*)&rr[4] = *(const float4*)&r_s[h * RS + rrow0 + 4];
#pragma unroll
                for (int i = 0; i < 4; i++)
#pragma unroll
                    for (int j = 0; j < 4; j++) {
                        qk[i][j]  = fmaf(au_[i][hh], kk_[j], qk[i][j]);
                        bbx[i][j] = fmaf(av_[i][hh], rr[j - i + 3], bbx[i][j]);
                    }
            }
        }
        float lv[4][4];
#pragma unroll
        for (int i = 0; i < 4; i++) {
            int tg = t0 + qbase + i;
#pragma unroll
            for (int j = 0; j < 4; j++) {
                int sg = s0 + sbase + j;
                float l = __bfloat162float(__float2bfloat16(qk[i][j])) * SCALE + bbx[i][j] * SCALE;
                bool ok = (sg <= MM + tg) && (qi_s[qbase + i] == ki_s[sbase + j]);
                l = ok ? l : NEGINF;
                lv[i][j] = l;
                g_logits[((size_t)bn * TT + tg) * SS + sg] = l;
            }
        }
#pragma unroll
        for (int i = 0; i < 4; i++) {
            float tm = fmaxf(fmaxf(lv[i][0], lv[i][1]), fmaxf(lv[i][2], lv[i][3]));
#pragma unroll
            for (int msk = 1; msk < 16; msk <<= 1)
                tm = fmaxf(tm, __shfl_xor_sync(0xffffffffu, tm, msk));
            float nm = fmaxf(rmax[i], tm);
            float ps = expf(lv[i][0] - nm) + expf(lv[i][1] - nm) +
                       expf(lv[i][2] - nm) + expf(lv[i][3] - nm);
#pragma unroll
            for (int msk = 1; msk < 16; msk <<= 1)
                ps += __shfl_xor_sync(0xffffffffu, ps, msk);
            rsum[i] = rsum[i] * expf(rmax[i] - nm) + ps;
            rmax[i] = nm;
        }
    }
    if (tx == 0) {
#pragma unroll
        for (int i = 0; i < 4; i++) {
            rm_s[qbase + i] = rmax[i];
            rs_s[qbase + i] = rsum[i];
        }
    }
    __syncthreads();

    // ---------- phase 2 ----------
    float* p_s = qu_s;    // [q][s] stride 68
    float* v_s = qv_s;    // [s][h] stride 68
    float acc[4][4];
#pragma unroll
    for (int i = 0; i < 4; i++)
#pragma unroll
        for (int j = 0; j < 4; j++) acc[i][j] = 0.f;

    for (int s0 = 0; s0 < SS; s0 += 64) {
        if (s0 > causal_max) break;
        {
            int klo = g_ki[b * SS + s0];
            int khi = g_ki[b * SS + s0 + 63];
            if (khi < qlo || klo > qhi) continue;
        }
        __syncthreads();
        for (int e = tid; e < 4096; e += 256) {
            int q = e >> 6, s = e & 63;
            float L = g_logits[((size_t)bn * TT + t0 + q) * SS + s0 + s];
            float p = expf(L - rm_s[q]) / rs_s[q];
            p_s[q * QS + s] = __bfloat162float(__float2bfloat16(p));
        }
        for (int e = tid; e < 4096; e += 256) {
            int s = e >> 6, h = e & 63;
            v_s[s * QS + h] = __bfloat162float(g_vb[(size_t)(b * SS + s0 + s) * NH + n * 64 + h]);
        }
        __syncthreads();
#pragma unroll 4
        for (int s4 = 0; s4 < 16; s4++) {
            float pv_[4][4], vv_[4][4];
#pragma unroll
            for (int i = 0; i < 4; i++)
                *(float4*)&pv_[i][0] = *(const float4*)&p_s[(qbase + i) * QS + s4 * 4];
#pragma unroll
            for (int sj = 0; sj < 4; sj++)
                *(float4*)&vv_[sj][0] = *(const float4*)&v_s[(s4 * 4 + sj) * QS + sbase];
#pragma unroll
            for (int sj = 0; sj < 4; sj++)
#pragma unroll
                for (int i = 0; i < 4; i++)
#pragma unroll
                    for (int j = 0; j < 4; j++)
                        acc[i][j] = fmaf(pv_[i][sj], vv_[sj][j], acc[i][j]);
        }
    }
#pragma unroll
    for (int i = 0; i < 4; i++) {
        int t = t0 + qbase + i;
#pragma unroll
        for (int j = 0; j < 4; j++) {
            g_attnb[(size_t)(b * TT + t) * NH + n * 64 + sbase + j] =
                __float2bfloat16(acc[i][j]);
        }
    }
}

// ======================= launch =======================
extern "C" void kernel_launch(void* const* d_in, const int* in_sizes, int n_in,
                              void* d_out, int out_size)
{
    const float* x    = (const float*)d_in[0];
    const float* rel  = (const float*)d_in[1];
    const float* mem  = (const float*)d_in[2];
    const int*   ep   = (const int*)d_in[3];
    const int*   dones= (const int*)d_in[4];
    const float* Wq   = (const float*)d_in[5];
    const float* Wk   = (const float*)d_in[6];
    const float* Wv   = (const float*)d_in[7];
    const float* Wr   = (const float*)d_in[8];
    const float* u    = (const float*)d_in[9];
    const float* v    = (const float*)d_in[10];
    const float* Wout = (const float*)d_in[11];
    const float* bo   = (const float*)d_in[12];
    float* out = (float*)d_out;
    (void)in_sizes; (void)n_in; (void)out_size;

    // launches #1..#3 (att_fused is launch #4 for the profiler window)
    prep_kv<<<BB * SS, 256>>>(x, mem);
    prep_rest<<<2048 + 5120 + 2, 256>>>(rel, Wq, Wk, Wv, Wr, Wout, ep, dones);

    cudaFuncSetAttribute(proj_gemm, cudaFuncAttributeMaxDynamicSharedMemorySize, PJ_SMEM);
    proj_gemm<<<dim3(8, 96), 256, PJ_SMEM>>>(v, u);

    cudaFuncSetAttribute(att_fused, cudaFuncAttributeMaxDynamicSharedMemorySize, ATT_SMEM);
    att_fused<<<dim3(BB * NHEAD, TT / 64), 256, ATT_SMEM>>>(ep);

    cudaFuncSetAttribute(out_gemm, cudaFuncAttributeMaxDynamicSharedMemorySize, PO_SMEM);
    out_gemm<<<dim3(8, 32), 256, PO_SMEM>>>(bo, out);
}